// round 5
// baseline (speedup 1.0000x reference)
#include <cuda_runtime.h>

#define BDIM 8
#define CDIM 192
#define C3 576
#define NPIX 16384
#define NH 4
#define CPH 48
#define NSPLIT 16

// ---- scratch (device globals; no allocation allowed) ----
__device__ float g_qkv[(size_t)BDIM * C3 * NPIX];     // after 1x1 conv
__device__ float g_dw [(size_t)BDIM * C3 * NPIX];     // after depthwise 3x3
__device__ float g_invnorm[2 * BDIM * CDIM];          // [q|k][b][c] reciprocal norms
__device__ float g_spart[(size_t)BDIM * NH * NSPLIT * CPH * CPH];
__device__ float g_attn [(size_t)BDIM * NH * CPH * CPH];
__device__ float g_M    [(size_t)BDIM * CDIM * CDIM]; // proj @ blockdiag(attn)

// ---------------------------------------------------------------------------
// Batched SGEMM: Y[b] = W[b](MxK) @ X[b](KxN).  64x64 tile, BK=16, 4x4 micro.
// ---------------------------------------------------------------------------
__global__ __launch_bounds__(256) void gemm64(
    const float* __restrict__ Wp, long wstride,
    const float* __restrict__ Xp, long xstride,
    float* __restrict__ Yp, long ystride,
    int M, int K, int N)
{
    const float* Wb = Wp + (long)blockIdx.z * wstride;
    const float* Xb = Xp + (long)blockIdx.z * xstride;
    float*       Yb = Yp + (long)blockIdx.z * ystride;
    const int m0 = blockIdx.y * 64;
    const int n0 = blockIdx.x * 64;

    __shared__ float As[16][64];
    __shared__ float Bs[16][64];

    const int tx = threadIdx.x, ty = threadIdx.y;
    const int tid = ty * 16 + tx;

    float acc[4][4];
#pragma unroll
    for (int i = 0; i < 4; i++)
#pragma unroll
        for (int j = 0; j < 4; j++) acc[i][j] = 0.f;

    for (int k0 = 0; k0 < K; k0 += 16) {
#pragma unroll
        for (int i = 0; i < 4; i++) {
            int idx = tid + i * 256;          // 0..1023
            int kk = idx >> 6, mn = idx & 63;
            As[kk][mn] = Wb[(long)(m0 + mn) * K + k0 + kk];
            Bs[kk][mn] = Xb[(long)(k0 + kk) * N + n0 + mn];
        }
        __syncthreads();
#pragma unroll
        for (int kk = 0; kk < 16; kk++) {
            float4 a4 = *(const float4*)&As[kk][ty * 4];
            float4 b4 = *(const float4*)&Bs[kk][tx * 4];
            float av[4] = {a4.x, a4.y, a4.z, a4.w};
            float bv[4] = {b4.x, b4.y, b4.z, b4.w};
#pragma unroll
            for (int i = 0; i < 4; i++)
#pragma unroll
                for (int j = 0; j < 4; j++)
                    acc[i][j] = fmaf(av[i], bv[j], acc[i][j]);
        }
        __syncthreads();
    }

#pragma unroll
    for (int i = 0; i < 4; i++) {
        int m = m0 + ty * 4 + i;
#pragma unroll
        for (int j = 0; j < 4; j++)
            Yb[(long)m * N + n0 + tx * 4 + j] = acc[i][j];
    }
}

// ---------------------------------------------------------------------------
// Depthwise 3x3, pad 1 (cross-correlation, matches lax.conv_general_dilated)
// ---------------------------------------------------------------------------
__global__ __launch_bounds__(256) void dwconv(
    const float* __restrict__ in, const float* __restrict__ w,
    float* __restrict__ out)
{
    const int bc = blockIdx.z;             // b*576 + ch
    const int ch = bc % C3;
    const float* ip = in + (size_t)bc * NPIX;
    float*       op = out + (size_t)bc * NPIX;
    const float* wp = w + ch * 9;

    const int x = blockIdx.x * 32 + threadIdx.x;
    const int y = blockIdx.y * 8 + threadIdx.y;

    float s = 0.f;
#pragma unroll
    for (int dy = -1; dy <= 1; dy++) {
        int yy = y + dy;
        if ((unsigned)yy < 128u) {
#pragma unroll
            for (int dx = -1; dx <= 1; dx++) {
                int xx = x + dx;
                if ((unsigned)xx < 128u)
                    s = fmaf(__ldg(wp + (dy + 1) * 3 + dx + 1), ip[yy * 128 + xx], s);
            }
        }
    }
    op[y * 128 + x] = s;
}

// ---------------------------------------------------------------------------
// Row reciprocal L2 norms of q (which=0) and k (which=1) rows
// ---------------------------------------------------------------------------
__global__ __launch_bounds__(256) void rownorm(
    const float* __restrict__ dw, float* __restrict__ invn)
{
    const int r = blockIdx.x;                  // 0 .. 2*8*192-1
    const int which = r / (BDIM * CDIM);
    const int rr = r % (BDIM * CDIM);
    const int b = rr / CDIM, c = rr % CDIM;
    const float* p = dw + ((size_t)b * C3 + which * CDIM + c) * NPIX;

    float s = 0.f;
    for (int i = threadIdx.x; i < NPIX; i += 256) {
        float v = p[i];
        s = fmaf(v, v, s);
    }
    __shared__ float red[256];
    red[threadIdx.x] = s;
    __syncthreads();
    for (int off = 128; off; off >>= 1) {
        if (threadIdx.x < off) red[threadIdx.x] += red[threadIdx.x + off];
        __syncthreads();
    }
    if (threadIdx.x == 0)
        invn[r] = 1.0f / fmaxf(sqrtf(red[0]), 1e-12f);
}

// ---------------------------------------------------------------------------
// Partial S[c,d] = sum_n q[c,n]*k[d,n] over a 1/NSPLIT slice of n
// One block per (b,h,split); 16x16 threads, 3x3 accum each (48x48 output)
// ---------------------------------------------------------------------------
__global__ __launch_bounds__(256) void attn_part(
    const float* __restrict__ dw, float* __restrict__ spart)
{
    const int bh = blockIdx.x;
    const int b = bh >> 2, h = bh & 3;
    const int split = blockIdx.y;
    const float* qb = dw + ((size_t)b * C3 + h * CPH) * NPIX;
    const float* kb = dw + ((size_t)b * C3 + CDIM + h * CPH) * NPIX;

    __shared__ float qs[32][CPH + 1];
    __shared__ float ks[32][CPH + 1];

    const int tx = threadIdx.x, ty = threadIdx.y;
    const int tid = ty * 16 + tx;

    float acc[3][3] = {};
    const int nbeg = split * (NPIX / NSPLIT);
    for (int n0 = nbeg; n0 < nbeg + NPIX / NSPLIT; n0 += 32) {
#pragma unroll
        for (int i = 0; i < 6; i++) {
            int idx = tid + i * 256;      // 0..1535
            int c = idx >> 5, kk = idx & 31;
            qs[kk][c] = qb[(size_t)c * NPIX + n0 + kk];
            ks[kk][c] = kb[(size_t)c * NPIX + n0 + kk];
        }
        __syncthreads();
#pragma unroll
        for (int kk = 0; kk < 32; kk++) {
            float qa[3], kv[3];
#pragma unroll
            for (int i = 0; i < 3; i++) qa[i] = qs[kk][ty * 3 + i];
#pragma unroll
            for (int j = 0; j < 3; j++) kv[j] = ks[kk][tx * 3 + j];
#pragma unroll
            for (int i = 0; i < 3; i++)
#pragma unroll
                for (int j = 0; j < 3; j++)
                    acc[i][j] = fmaf(qa[i], kv[j], acc[i][j]);
        }
        __syncthreads();
    }

    float* sp = spart + ((size_t)(bh * NSPLIT + split)) * CPH * CPH;
#pragma unroll
    for (int i = 0; i < 3; i++)
#pragma unroll
        for (int j = 0; j < 3; j++)
            sp[(ty * 3 + i) * CPH + tx * 3 + j] = acc[i][j];
}

// ---------------------------------------------------------------------------
// Reduce split-K partials, apply norms + temperature, softmax over d
// ---------------------------------------------------------------------------
__global__ void attn_fin(
    const float* __restrict__ spart, const float* __restrict__ invn,
    const float* __restrict__ temp, float* __restrict__ attn)
{
    const int bh = blockIdx.x;
    const int b = bh >> 2, h = bh & 3;
    const int c = threadIdx.x;
    if (c >= CPH) return;

    const float invq = invn[b * CDIM + h * CPH + c];
    const float t = temp[h];
    const float* base = spart + (size_t)bh * NSPLIT * CPH * CPH + c * CPH;

    float vals[CPH];
    float mx = -1e30f;
#pragma unroll
    for (int d = 0; d < CPH; d++) {
        float s = 0.f;
        for (int sp = 0; sp < NSPLIT; sp++)
            s += base[sp * CPH * CPH + d];
        float invk = invn[BDIM * CDIM + b * CDIM + h * CPH + d];
        float v = s * invq * invk * t;
        vals[d] = v;
        mx = fmaxf(mx, v);
    }
    float sum = 0.f;
#pragma unroll
    for (int d = 0; d < CPH; d++) {
        vals[d] = expf(vals[d] - mx);
        sum += vals[d];
    }
    const float inv = 1.f / sum;
    float* ap = attn + (size_t)bh * CPH * CPH + c * CPH;
#pragma unroll
    for (int d = 0; d < CPH; d++) ap[d] = vals[d] * inv;
}

// ---------------------------------------------------------------------------
// M[b] = proj_w @ blockdiag(attn[b,h])  (192x192 per batch)
// ---------------------------------------------------------------------------
__global__ __launch_bounds__(256) void make_M(
    const float* __restrict__ proj, const float* __restrict__ attn,
    float* __restrict__ Mout)
{
    const int b = blockIdx.x, h = blockIdx.y;
    __shared__ float sA[CPH * CPH];
    const int tid = threadIdx.x;
    const float* ap = attn + ((size_t)(b * NH + h)) * CPH * CPH;
    for (int i = tid; i < CPH * CPH; i += 256) sA[i] = ap[i];
    __syncthreads();

    for (int idx = tid; idx < CDIM * CPH; idx += 256) {
        int oc = idx / CPH, d = idx % CPH;
        float s = 0.f;
#pragma unroll
        for (int c = 0; c < CPH; c++)
            s = fmaf(proj[oc * CDIM + h * CPH + c], sA[c * CPH + d], s);
        Mout[(size_t)b * CDIM * CDIM + oc * CDIM + h * CPH + d] = s;
    }
}

// ---------------------------------------------------------------------------
extern "C" void kernel_launch(void* const* d_in, const int* in_sizes, int n_in,
                              void* d_out, int out_size)
{
    const float* x      = (const float*)d_in[0];
    const float* qkv_w  = (const float*)d_in[1];
    const float* dw_w   = (const float*)d_in[2];
    const float* proj_w = (const float*)d_in[3];
    const float* temp   = (const float*)d_in[4];
    float* out = (float*)d_out;

    float *qkvp, *dwp, *invnp, *spartp, *attnp, *Mp;
    cudaGetSymbolAddress((void**)&qkvp,  g_qkv);
    cudaGetSymbolAddress((void**)&dwp,   g_dw);
    cudaGetSymbolAddress((void**)&invnp, g_invnorm);
    cudaGetSymbolAddress((void**)&spartp, g_spart);
    cudaGetSymbolAddress((void**)&attnp, g_attn);
    cudaGetSymbolAddress((void**)&Mp,    g_M);

    dim3 blk(16, 16);

    // 1) qkv = 1x1 conv: [576,192] @ [192,16384] per batch
    gemm64<<<dim3(NPIX / 64, C3 / 64, BDIM), blk>>>(
        qkv_w, 0L, x, (long)CDIM * NPIX, qkvp, (long)C3 * NPIX,
        C3, CDIM, NPIX);

    // 2) depthwise 3x3
    dwconv<<<dim3(128 / 32, 128 / 8, BDIM * C3), dim3(32, 8)>>>(
        qkvp, dw_w, dwp);

    // 3) reciprocal row norms for q and k
    rownorm<<<2 * BDIM * CDIM, 256>>>(dwp, invnp);

    // 4) S = q @ k^T  (split-K partials)
    attn_part<<<dim3(BDIM * NH, NSPLIT), blk>>>(dwp, spartp);

    // 5) normalize + temperature + softmax
    attn_fin<<<BDIM * NH, 64>>>(spartp, invnp, temp, attnp);

    // 6) M[b] = proj @ blockdiag(attn)
    make_M<<<dim3(BDIM, NH), 256>>>(proj_w, attnp, Mp);

    // 7) out[b] = M[b] @ v[b]   (v = channels 384..575 of g_dw)
    gemm64<<<dim3(NPIX / 64, CDIM / 64, BDIM), blk>>>(
        Mp, (long)CDIM * CDIM,
        dwp + (size_t)2 * CDIM * NPIX, (long)C3 * NPIX,
        out, (long)CDIM * NPIX,
        CDIM, CDIM, NPIX);
}

// round 7
// speedup vs baseline: 2.1883x; 2.1883x over previous
#include <cuda_runtime.h>
#include <cuda_bf16.h>
#include <cstdint>

#define BDIM 8
#define CDIM 192
#define C3 576
#define NPIX 16384
#define NH 4
#define CPH 48
#define NSPLIT 16
#define KTOT 192

// ---- scratch (device globals; no allocation allowed) ----
__device__ float g_qkv[(size_t)BDIM * C3 * NPIX];     // after 1x1 conv
__device__ float g_dw [(size_t)BDIM * C3 * NPIX];     // after depthwise 3x3
__device__ float g_sq [(size_t)BDIM * 2 * CDIM];      // q/k sum of squares
__device__ float g_invnorm[2 * BDIM * CDIM];          // reciprocal norms
__device__ float g_spart[(size_t)BDIM * NH * NSPLIT * CPH * CPH];
__device__ float g_attn [(size_t)BDIM * NH * CPH * CPH];
__device__ float g_M    [(size_t)BDIM * CDIM * CDIM]; // proj @ blockdiag(attn)

// ======================= HMMA helpers (sm_80+ family-safe) =================
__device__ __forceinline__ void ldsm_x4(uint32_t* r, uint32_t addr) {
    asm volatile("ldmatrix.sync.aligned.m8n8.x4.shared.b16 {%0,%1,%2,%3}, [%4];"
        : "=r"(r[0]), "=r"(r[1]), "=r"(r[2]), "=r"(r[3]) : "r"(addr));
}
__device__ __forceinline__ void ldsm_x4t(uint32_t* r, uint32_t addr) {
    asm volatile("ldmatrix.sync.aligned.m8n8.x4.trans.shared.b16 {%0,%1,%2,%3}, [%4];"
        : "=r"(r[0]), "=r"(r[1]), "=r"(r[2]), "=r"(r[3]) : "r"(addr));
}
__device__ __forceinline__ void mma16816(float* c, const uint32_t* a,
                                         const uint32_t* b) {
    asm volatile(
        "mma.sync.aligned.m16n8k16.row.col.f32.bf16.bf16.f32 "
        "{%0,%1,%2,%3}, {%4,%5,%6,%7}, {%8,%9}, {%0,%1,%2,%3};"
        : "+f"(c[0]), "+f"(c[1]), "+f"(c[2]), "+f"(c[3])
        : "r"(a[0]), "r"(a[1]), "r"(a[2]), "r"(a[3]), "r"(b[0]), "r"(b[1]));
}
__device__ __forceinline__ uint32_t pack2(float a, float b) {
    __nv_bfloat162 t = __floats2bfloat162_rn(a, b);
    return *(uint32_t*)&t;
}

// ===========================================================================
// HMMA batched SGEMM (bf16 2-way split, 3 products => ~fp32 accuracy)
// Y[b](Mrows x N) = W[b](Mrows x 192) @ X[b](192 x N)
// CTA 128x128 tile, 8 warps (4m x 2n), warp tile 32x64, K-chunks of 32.
// ===========================================================================
#define ASTR 40    // A smem row stride in bf16 (80B: conflict-free ldmatrix)
#define BSTR 136   // B smem row stride in bf16 (272B: conflict-free ldmatrix)

__global__ __launch_bounds__(256, 1)
void gemm_tc(const float* __restrict__ Wp, long wstride,
             const float* __restrict__ Xp, long xstride,
             float* __restrict__ Yp, long ystride,
             int Mrows, int N)
{
    __shared__ __nv_bfloat16 Ah[128][ASTR], Al[128][ASTR];
    __shared__ __nv_bfloat16 Bh[32][BSTR],  Bl[32][BSTR];

    const int tid = threadIdx.x, lane = tid & 31, wid = tid >> 5;
    const int mw = (wid & 3) * 32;       // warp m-offset in tile
    const int nw = (wid >> 2) * 64;      // warp n-offset in tile
    const int m0 = blockIdx.y * 128, n0 = blockIdx.x * 128;
    const float* Wb = Wp + (long)blockIdx.z * wstride;
    const float* Xb = Xp + (long)blockIdx.z * xstride;
    float*       Yb = Yp + (long)blockIdx.z * ystride;

    const uint32_t sAh = (uint32_t)__cvta_generic_to_shared(&Ah[0][0]);
    const uint32_t sAl = (uint32_t)__cvta_generic_to_shared(&Al[0][0]);
    const uint32_t sBh = (uint32_t)__cvta_generic_to_shared(&Bh[0][0]);
    const uint32_t sBl = (uint32_t)__cvta_generic_to_shared(&Bl[0][0]);

    // ldmatrix per-lane address components (elements, *2 for bytes later)
    const int arow0 = (mw + (lane & 15)) * ASTR + ((lane >> 4) << 3);
    const int arow1 = arow0 + 16 * ASTR;
    const int brow  = (lane & 15) * BSTR + nw + ((lane >> 4) << 3);

    float acc[2][8][4];
#pragma unroll
    for (int i = 0; i < 2; i++)
#pragma unroll
        for (int j = 0; j < 8; j++)
#pragma unroll
            for (int q = 0; q < 4; q++) acc[i][j][q] = 0.f;

    for (int kc = 0; kc < KTOT; kc += 32) {
        // ---- load + split A (128 x 32) ----
#pragma unroll
        for (int it = 0; it < 4; it++) {
            int idx = tid + it * 256;           // 0..1023 float4 slots
            int m = idx >> 3, kq = idx & 7;
            int gm = m0 + m;
            float4 v = make_float4(0.f, 0.f, 0.f, 0.f);
            if (gm < Mrows)
                v = *(const float4*)&Wb[(long)gm * KTOT + kc + kq * 4];
            float vv[4] = {v.x, v.y, v.z, v.w};
            float hi[4], lo[4];
#pragma unroll
            for (int j = 0; j < 4; j++) {
                __nv_bfloat16 h = __float2bfloat16_rn(vv[j]);
                hi[j] = __bfloat162float(h);
                lo[j] = vv[j] - hi[j];
            }
            *(uint2*)&Ah[m][kq * 4] = make_uint2(pack2(hi[0], hi[1]),
                                                 pack2(hi[2], hi[3]));
            *(uint2*)&Al[m][kq * 4] = make_uint2(pack2(lo[0], lo[1]),
                                                 pack2(lo[2], lo[3]));
        }
        // ---- load + split B (32 x 128) ----
#pragma unroll
        for (int it = 0; it < 4; it++) {
            int idx = tid + it * 256;
            int k = idx >> 5, nq = idx & 31;
            float4 v = *(const float4*)&Xb[(long)(kc + k) * N + n0 + nq * 4];
            float vv[4] = {v.x, v.y, v.z, v.w};
            float hi[4], lo[4];
#pragma unroll
            for (int j = 0; j < 4; j++) {
                __nv_bfloat16 h = __float2bfloat16_rn(vv[j]);
                hi[j] = __bfloat162float(h);
                lo[j] = vv[j] - hi[j];
            }
            *(uint2*)&Bh[k][nq * 4] = make_uint2(pack2(hi[0], hi[1]),
                                                 pack2(hi[2], hi[3]));
            *(uint2*)&Bl[k][nq * 4] = make_uint2(pack2(lo[0], lo[1]),
                                                 pack2(lo[2], lo[3]));
        }
        __syncthreads();

#pragma unroll
        for (int ks = 0; ks < 32; ks += 16) {
            uint32_t ah[2][4], al[2][4], bh[8][2], bl[8][2];
            ldsm_x4(ah[0], sAh + (uint32_t)(arow0 + ks) * 2);
            ldsm_x4(ah[1], sAh + (uint32_t)(arow1 + ks) * 2);
            ldsm_x4(al[0], sAl + (uint32_t)(arow0 + ks) * 2);
            ldsm_x4(al[1], sAl + (uint32_t)(arow1 + ks) * 2);
#pragma unroll
            for (int p = 0; p < 4; p++) {
                uint32_t r[4];
                ldsm_x4t(r, sBh + (uint32_t)(brow + ks * BSTR + p * 16) * 2);
                bh[2 * p][0] = r[0]; bh[2 * p][1] = r[1];
                bh[2 * p + 1][0] = r[2]; bh[2 * p + 1][1] = r[3];
                ldsm_x4t(r, sBl + (uint32_t)(brow + ks * BSTR + p * 16) * 2);
                bl[2 * p][0] = r[0]; bl[2 * p][1] = r[1];
                bl[2 * p + 1][0] = r[2]; bl[2 * p + 1][1] = r[3];
            }
#pragma unroll
            for (int mf = 0; mf < 2; mf++)
#pragma unroll
                for (int nf = 0; nf < 8; nf++) {
                    mma16816(acc[mf][nf], ah[mf], bh[nf]);  // hi*hi
                    mma16816(acc[mf][nf], ah[mf], bl[nf]);  // hi*lo
                    mma16816(acc[mf][nf], al[mf], bh[nf]);  // lo*hi
                }
        }
        __syncthreads();
    }

    // ---- epilogue: direct STG (fragment layout) ----
#pragma unroll
    for (int mf = 0; mf < 2; mf++) {
        int r0 = m0 + mw + mf * 16 + (lane >> 2);
#pragma unroll
        for (int nf = 0; nf < 8; nf++) {
            int c = n0 + nw + nf * 8 + (lane & 3) * 2;
            if (r0 < Mrows)
                *(float2*)&Yb[(long)r0 * N + c] =
                    make_float2(acc[mf][nf][0], acc[mf][nf][1]);
            if (r0 + 8 < Mrows)
                *(float2*)&Yb[(long)(r0 + 8) * N + c] =
                    make_float2(acc[mf][nf][2], acc[mf][nf][3]);
        }
    }
}

// ---------------------------------------------------------------------------
// Depthwise 3x3, pad 1; fused q/k sum-of-squares partial reduction
// ---------------------------------------------------------------------------
__global__ __launch_bounds__(256) void dwconv(
    const float* __restrict__ in, const float* __restrict__ w,
    float* __restrict__ out, float* __restrict__ sq)
{
    const int bc = blockIdx.z;             // b*576 + ch
    const int ch = bc % C3;
    const int b = bc / C3;
    const float* ip = in + (size_t)bc * NPIX;
    float*       op = out + (size_t)bc * NPIX;
    const float* wp = w + ch * 9;

    const int x = blockIdx.x * 32 + threadIdx.x;
    const int y = blockIdx.y * 8 + threadIdx.y;

    float s = 0.f;
#pragma unroll
    for (int dy = -1; dy <= 1; dy++) {
        int yy = y + dy;
        if ((unsigned)yy < 128u) {
#pragma unroll
            for (int dx = -1; dx <= 1; dx++) {
                int xx = x + dx;
                if ((unsigned)xx < 128u)
                    s = fmaf(__ldg(wp + (dy + 1) * 3 + dx + 1), ip[yy * 128 + xx], s);
            }
        }
    }
    op[y * 128 + x] = s;

    if (ch < 2 * CDIM) {
        __shared__ float red[256];
        int t = threadIdx.y * 32 + threadIdx.x;
        red[t] = s * s;
        __syncthreads();
        for (int off = 128; off; off >>= 1) {
            if (t < off) red[t] += red[t + off];
            __syncthreads();
        }
        if (t == 0) atomicAdd(&sq[b * 2 * CDIM + ch], red[0]);
    }
}

__global__ void zero_sq(float* __restrict__ sq) {
    int i = blockIdx.x * 256 + threadIdx.x;
    if (i < BDIM * 2 * CDIM) sq[i] = 0.f;
}

__global__ void finalize_norm(const float* __restrict__ sq,
                              float* __restrict__ invn)
{
    int idx = blockIdx.x * 256 + threadIdx.x;
    if (idx >= 2 * BDIM * CDIM) return;
    int which = idx / (BDIM * CDIM);
    int r = idx % (BDIM * CDIM);
    int b = r / CDIM, c = r % CDIM;
    float s = sq[b * 2 * CDIM + which * CDIM + c];
    invn[idx] = 1.0f / fmaxf(sqrtf(s), 1e-12f);
}

// ---------------------------------------------------------------------------
// Partial S[c,d] = sum_n q[c,n]*k[d,n] over a 1/NSPLIT slice of n
// ---------------------------------------------------------------------------
__global__ __launch_bounds__(256) void attn_part(
    const float* __restrict__ dw, float* __restrict__ spart)
{
    const int bh = blockIdx.x;
    const int b = bh >> 2, h = bh & 3;
    const int split = blockIdx.y;
    const float* qb = dw + ((size_t)b * C3 + h * CPH) * NPIX;
    const float* kb = dw + ((size_t)b * C3 + CDIM + h * CPH) * NPIX;

    __shared__ float qs[32][CPH + 1];
    __shared__ float ks[32][CPH + 1];

    const int tx = threadIdx.x, ty = threadIdx.y;
    const int tid = ty * 16 + tx;

    float acc[3][3] = {};
    const int nbeg = split * (NPIX / NSPLIT);
    for (int n0 = nbeg; n0 < nbeg + NPIX / NSPLIT; n0 += 32) {
#pragma unroll
        for (int i = 0; i < 6; i++) {
            int idx = tid + i * 256;
            int c = idx >> 5, kk = idx & 31;
            qs[kk][c] = qb[(size_t)c * NPIX + n0 + kk];
            ks[kk][c] = kb[(size_t)c * NPIX + n0 + kk];
        }
        __syncthreads();
#pragma unroll
        for (int kk = 0; kk < 32; kk++) {
            float qa[3], kv[3];
#pragma unroll
            for (int i = 0; i < 3; i++) qa[i] = qs[kk][ty * 3 + i];
#pragma unroll
            for (int j = 0; j < 3; j++) kv[j] = ks[kk][tx * 3 + j];
#pragma unroll
            for (int i = 0; i < 3; i++)
#pragma unroll
                for (int j = 0; j < 3; j++)
                    acc[i][j] = fmaf(qa[i], kv[j], acc[i][j]);
        }
        __syncthreads();
    }

    float* sp = spart + ((size_t)(bh * NSPLIT + split)) * CPH * CPH;
#pragma unroll
    for (int i = 0; i < 3; i++)
#pragma unroll
        for (int j = 0; j < 3; j++)
            sp[(ty * 3 + i) * CPH + tx * 3 + j] = acc[i][j];
}

// ---------------------------------------------------------------------------
// Reduce split-K partials, apply norms + temperature, softmax over d
// ---------------------------------------------------------------------------
__global__ void attn_fin(
    const float* __restrict__ spart, const float* __restrict__ invn,
    const float* __restrict__ temp, float* __restrict__ attn)
{
    const int bh = blockIdx.x;
    const int b = bh >> 2, h = bh & 3;
    const int c = threadIdx.x;
    if (c >= CPH) return;

    const float invq = invn[b * CDIM + h * CPH + c];
    const float t = temp[h];
    const float* base = spart + (size_t)bh * NSPLIT * CPH * CPH + c * CPH;

    float vals[CPH];
    float mx = -1e30f;
#pragma unroll
    for (int d = 0; d < CPH; d++) {
        float s = 0.f;
        for (int sp = 0; sp < NSPLIT; sp++)
            s += base[sp * CPH * CPH + d];
        float invk = invn[BDIM * CDIM + b * CDIM + h * CPH + d];
        float v = s * invq * invk * t;
        vals[d] = v;
        mx = fmaxf(mx, v);
    }
    float sum = 0.f;
#pragma unroll
    for (int d = 0; d < CPH; d++) {
        vals[d] = expf(vals[d] - mx);
        sum += vals[d];
    }
    const float inv = 1.f / sum;
    float* ap = attn + (size_t)bh * CPH * CPH + c * CPH;
#pragma unroll
    for (int d = 0; d < CPH; d++) ap[d] = vals[d] * inv;
}

// ---------------------------------------------------------------------------
// M[b] = proj_w @ blockdiag(attn[b,h])  (192x192 per batch)
// ---------------------------------------------------------------------------
__global__ __launch_bounds__(256) void make_M(
    const float* __restrict__ proj, const float* __restrict__ attn,
    float* __restrict__ Mout)
{
    const int b = blockIdx.x, h = blockIdx.y;
    __shared__ float sA[CPH * CPH];
    const int tid = threadIdx.x;
    const float* ap = attn + ((size_t)(b * NH + h)) * CPH * CPH;
    for (int i = tid; i < CPH * CPH; i += 256) sA[i] = ap[i];
    __syncthreads();

    for (int idx = tid; idx < CDIM * CPH; idx += 256) {
        int oc = idx / CPH, d = idx % CPH;
        float s = 0.f;
#pragma unroll
        for (int c = 0; c < CPH; c++)
            s = fmaf(proj[oc * CDIM + h * CPH + c], sA[c * CPH + d], s);
        Mout[(size_t)b * CDIM * CDIM + oc * CDIM + h * CPH + d] = s;
    }
}

// ---------------------------------------------------------------------------
extern "C" void kernel_launch(void* const* d_in, const int* in_sizes, int n_in,
                              void* d_out, int out_size)
{
    const float* x      = (const float*)d_in[0];
    const float* qkv_w  = (const float*)d_in[1];
    const float* dw_w   = (const float*)d_in[2];
    const float* proj_w = (const float*)d_in[3];
    const float* temp   = (const float*)d_in[4];
    float* out = (float*)d_out;

    float *qkvp, *dwp, *sqp, *invnp, *spartp, *attnp, *Mp;
    cudaGetSymbolAddress((void**)&qkvp,  g_qkv);
    cudaGetSymbolAddress((void**)&dwp,   g_dw);
    cudaGetSymbolAddress((void**)&sqp,   g_sq);
    cudaGetSymbolAddress((void**)&invnp, g_invnorm);
    cudaGetSymbolAddress((void**)&spartp, g_spart);
    cudaGetSymbolAddress((void**)&attnp, g_attn);
    cudaGetSymbolAddress((void**)&Mp,    g_M);

    // 1) qkv = 1x1 conv: [576,192] @ [192,16384] per batch (HMMA bf16-split)
    gemm_tc<<<dim3(NPIX / 128, 5, BDIM), 256>>>(
        qkv_w, 0L, x, (long)CDIM * NPIX, qkvp, (long)C3 * NPIX,
        C3, NPIX);

    // 2) depthwise 3x3 + fused q/k sum-of-squares
    zero_sq<<<(BDIM * 2 * CDIM + 255) / 256, 256>>>(sqp);
    dwconv<<<dim3(128 / 32, 128 / 8, BDIM * C3), dim3(32, 8)>>>(
        qkvp, dw_w, dwp, sqp);

    // 3) reciprocal row norms
    finalize_norm<<<(2 * BDIM * CDIM + 255) / 256, 256>>>(sqp, invnp);

    // 4) S = q @ k^T  (split-K partials)
    attn_part<<<dim3(BDIM * NH, NSPLIT), dim3(16, 16)>>>(dwp, spartp);

    // 5) normalize + temperature + softmax
    attn_fin<<<BDIM * NH, 64>>>(spartp, invnp, temp, attnp);

    // 6) M[b] = proj @ blockdiag(attn)
    make_M<<<dim3(BDIM, NH), 256>>>(proj_w, attnp, Mp);

    // 7) out[b] = M[b] @ v[b]   (HMMA; v = channels 384..575 of g_dw)
    gemm_tc<<<dim3(NPIX / 128, 2, BDIM), 256>>>(
        Mp, (long)CDIM * CDIM,
        dwp + (size_t)2 * CDIM * NPIX, (long)C3 * NPIX,
        out, (long)CDIM * NPIX,
        CDIM, NPIX);
}

// round 10
// speedup vs baseline: 2.2158x; 1.0126x over previous
#include <cuda_runtime.h>
#include <cuda_bf16.h>
#include <cstdint>

#define BDIM 8
#define CDIM 192
#define C3 576
#define NPIX 16384
#define NH 4
#define CPH 48
#define NSPLIT 16
#define KTOT 192
#define DW2 (2 * CDIM)   // q+k channels kept in fp32

// ---- scratch (device globals; no allocation allowed) ----
__device__ float g_qkv [(size_t)BDIM * C3 * NPIX];     // after 1x1 conv (fp32)
__device__ float g_dwqk[(size_t)BDIM * DW2 * NPIX];    // dwconv out, q|k only
__device__ __nv_bfloat16 g_vh[(size_t)BDIM * CDIM * NPIX];  // v split hi
__device__ __nv_bfloat16 g_vl[(size_t)BDIM * CDIM * NPIX];  // v split lo
__device__ __nv_bfloat16 g_xh[(size_t)BDIM * CDIM * NPIX];  // x split hi
__device__ __nv_bfloat16 g_xl[(size_t)BDIM * CDIM * NPIX];  // x split lo
__device__ __nv_bfloat16 g_wh[C3 * CDIM];              // qkv_w split hi
__device__ __nv_bfloat16 g_wl[C3 * CDIM];              // qkv_w split lo
__device__ __nv_bfloat16 g_Mh[(size_t)BDIM * CDIM * CDIM];
__device__ __nv_bfloat16 g_Ml[(size_t)BDIM * CDIM * CDIM];
__device__ float g_sq [(size_t)BDIM * 2 * CDIM];
__device__ float g_invnorm[2 * BDIM * CDIM];
__device__ float g_spart[(size_t)BDIM * NH * NSPLIT * CPH * CPH];
__device__ float g_attn [(size_t)BDIM * NH * CPH * CPH];

// ======================= helpers (sm_80+ family-safe) ======================
__device__ __forceinline__ void ldsm_x4(uint32_t* r, uint32_t addr) {
    asm volatile("ldmatrix.sync.aligned.m8n8.x4.shared.b16 {%0,%1,%2,%3}, [%4];"
        : "=r"(r[0]), "=r"(r[1]), "=r"(r[2]), "=r"(r[3]) : "r"(addr));
}
__device__ __forceinline__ void ldsm_x4t(uint32_t* r, uint32_t addr) {
    asm volatile("ldmatrix.sync.aligned.m8n8.x4.trans.shared.b16 {%0,%1,%2,%3}, [%4];"
        : "=r"(r[0]), "=r"(r[1]), "=r"(r[2]), "=r"(r[3]) : "r"(addr));
}
__device__ __forceinline__ void mma16816(float* c, const uint32_t* a,
                                         const uint32_t* b) {
    asm volatile(
        "mma.sync.aligned.m16n8k16.row.col.f32.bf16.bf16.f32 "
        "{%0,%1,%2,%3}, {%4,%5,%6,%7}, {%8,%9}, {%0,%1,%2,%3};"
        : "+f"(c[0]), "+f"(c[1]), "+f"(c[2]), "+f"(c[3])
        : "r"(a[0]), "r"(a[1]), "r"(a[2]), "r"(a[3]), "r"(b[0]), "r"(b[1]));
}
__device__ __forceinline__ uint32_t pack2(float a, float b) {
    __nv_bfloat162 t = __floats2bfloat162_rn(a, b);
    return *(uint32_t*)&t;
}
__device__ __forceinline__ void cpasync16(uint32_t dst, const void* src, int nb) {
    asm volatile("cp.async.cg.shared.global [%0], [%1], 16, %2;"
                 :: "r"(dst), "l"(src), "r"(nb));
}

// ===========================================================================
// Pipelined bf16 HMMA GEMM (pre-split inputs, 3 products = ~fp32 accuracy)
// Y[b](Mrows x N) = A[b](Mrows x 192) @ B[b](192 x N)
// CTA 128x128 tile, 8 warps (4m x 2n), K-chunks of 32, 2-stage cp.async.
// ===========================================================================
#define ASTR 40                       // A smem row stride (elems) - conflict-free
#define BSTR 136                      // B smem row stride (elems)
#define A_ST_B (128 * ASTR * 2)       // 10240 B  (one half, one stage)
#define B_ST_B (32 * BSTR * 2)        // 8704 B
#define SMEM_GEMM (4 * A_ST_B + 4 * B_ST_B)   // 75776 B

__global__ __launch_bounds__(256, 1)
void gemm_bf16(const __nv_bfloat16* __restrict__ Ahg,
               const __nv_bfloat16* __restrict__ Alg, long astride,
               const __nv_bfloat16* __restrict__ Bhg,
               const __nv_bfloat16* __restrict__ Blg, long bstride,
               float* __restrict__ Yp, long ystride, int Mrows, int N)
{
    extern __shared__ __align__(16) char sm[];
    const uint32_t sbase = (uint32_t)__cvta_generic_to_shared(sm);

    const int tid = threadIdx.x, lane = tid & 31, wid = tid >> 5;
    const int mw = (wid & 3) * 32, nw = (wid >> 2) * 64;
    const int m0 = blockIdx.y * 128, n0 = blockIdx.x * 128;
    Ahg += (long)blockIdx.z * astride;
    Alg += (long)blockIdx.z * astride;
    Bhg += (long)blockIdx.z * bstride;
    Blg += (long)blockIdx.z * bstride;
    float* Yb = Yp + (long)blockIdx.z * ystride;

    // per-lane ldmatrix address components (element units)
    const int arow0 = (mw + (lane & 15)) * ASTR + ((lane >> 4) << 3);
    const int arow1 = arow0 + 16 * ASTR;
    const int brow  = (lane & 15) * BSTR + nw + ((lane >> 4) << 3);

    float acc[2][8][4];
#pragma unroll
    for (int i = 0; i < 2; i++)
#pragma unroll
        for (int j = 0; j < 8; j++)
#pragma unroll
            for (int q = 0; q < 4; q++) acc[i][j][q] = 0.f;

#define LOAD_CHUNK(s, kc) do {                                               \
    uint32_t aB = sbase + (s) * 2 * A_ST_B;                                  \
    uint32_t bB = sbase + 4 * A_ST_B + (s) * 2 * B_ST_B;                     \
    _Pragma("unroll")                                                        \
    for (int it = 0; it < 2; it++) {                                         \
        int idx = tid + it * 256;          /* 0..511 */                      \
        int m = idx >> 2, slot = idx & 3;                                    \
        int gm = m0 + m;                                                     \
        uint32_t dst = aB + m * (ASTR * 2) + slot * 16;                      \
        int nb = (gm < Mrows) ? 16 : 0;                                      \
        cpasync16(dst,          Ahg + (long)gm * KTOT + (kc) + slot * 8, nb);\
        cpasync16(dst + A_ST_B, Alg + (long)gm * KTOT + (kc) + slot * 8, nb);\
    }                                                                        \
    _Pragma("unroll")                                                        \
    for (int it = 0; it < 2; it++) {                                         \
        int idx = tid + it * 256;                                            \
        int k = idx >> 4, slot = idx & 15;                                   \
        uint32_t dst = bB + k * (BSTR * 2) + slot * 16;                      \
        cpasync16(dst,          Bhg + (long)((kc) + k) * N + n0 + slot * 8, 16);\
        cpasync16(dst + B_ST_B, Blg + (long)((kc) + k) * N + n0 + slot * 8, 16);\
    }                                                                        \
    asm volatile("cp.async.commit_group;");                                  \
} while (0)

    LOAD_CHUNK(0, 0);

    for (int c = 0; c < KTOT / 32; c++) {
        if (c + 1 < KTOT / 32) {
            LOAD_CHUNK((c + 1) & 1, (c + 1) * 32);
            asm volatile("cp.async.wait_group 1;");
        } else {
            asm volatile("cp.async.wait_group 0;");
        }
        __syncthreads();

        const uint32_t aB = sbase + (c & 1) * 2 * A_ST_B;
        const uint32_t bB = sbase + 4 * A_ST_B + (c & 1) * 2 * B_ST_B;
        const uint32_t sAh = aB, sAl = aB + A_ST_B;
        const uint32_t sBh = bB, sBl = bB + B_ST_B;

#pragma unroll
        for (int ks = 0; ks < 32; ks += 16) {
            uint32_t ah[2][4], al[2][4], bh[8][2], bl[8][2];
            ldsm_x4(ah[0], sAh + (uint32_t)(arow0 + ks) * 2);
            ldsm_x4(ah[1], sAh + (uint32_t)(arow1 + ks) * 2);
            ldsm_x4(al[0], sAl + (uint32_t)(arow0 + ks) * 2);
            ldsm_x4(al[1], sAl + (uint32_t)(arow1 + ks) * 2);
#pragma unroll
            for (int p = 0; p < 4; p++) {
                uint32_t r[4];
                ldsm_x4t(r, sBh + (uint32_t)(brow + ks * BSTR + p * 16) * 2);
                bh[2 * p][0] = r[0]; bh[2 * p][1] = r[1];
                bh[2 * p + 1][0] = r[2]; bh[2 * p + 1][1] = r[3];
                ldsm_x4t(r, sBl + (uint32_t)(brow + ks * BSTR + p * 16) * 2);
                bl[2 * p][0] = r[0]; bl[2 * p][1] = r[1];
                bl[2 * p + 1][0] = r[2]; bl[2 * p + 1][1] = r[3];
            }
#pragma unroll
            for (int mf = 0; mf < 2; mf++)
#pragma unroll
                for (int nf = 0; nf < 8; nf++) {
                    mma16816(acc[mf][nf], ah[mf], bh[nf]);  // hi*hi
                    mma16816(acc[mf][nf], ah[mf], bl[nf]);  // hi*lo
                    mma16816(acc[mf][nf], al[mf], bh[nf]);  // lo*hi
                }
        }
        __syncthreads();
    }

    // ---- epilogue: direct STG (fragment layout) ----
#pragma unroll
    for (int mf = 0; mf < 2; mf++) {
        int r0 = m0 + mw + mf * 16 + (lane >> 2);
#pragma unroll
        for (int nf = 0; nf < 8; nf++) {
            int cidx = n0 + nw + nf * 8 + (lane & 3) * 2;
            if (r0 < Mrows)
                *(float2*)&Yb[(long)r0 * N + cidx] =
                    make_float2(acc[mf][nf][0], acc[mf][nf][1]);
            if (r0 + 8 < Mrows)
                *(float2*)&Yb[(long)(r0 + 8) * N + cidx] =
                    make_float2(acc[mf][nf][2], acc[mf][nf][3]);
        }
    }
}

// ---------------------------------------------------------------------------
// fp32 -> (hi, lo) bf16 split, vectorized (n4 = count/4)
// ---------------------------------------------------------------------------
__global__ __launch_bounds__(256) void split_f32(
    const float* __restrict__ in, __nv_bfloat16* __restrict__ hp,
    __nv_bfloat16* __restrict__ lp, int n4)
{
    int i = blockIdx.x * 256 + threadIdx.x;
    if (i >= n4) return;
    float4 v = ((const float4*)in)[i];
    float vv[4] = {v.x, v.y, v.z, v.w};
    float hi[4], lo[4];
#pragma unroll
    for (int j = 0; j < 4; j++) {
        __nv_bfloat16 h = __float2bfloat16_rn(vv[j]);
        hi[j] = __bfloat162float(h);
        lo[j] = vv[j] - hi[j];
    }
    ((uint2*)hp)[i] = make_uint2(pack2(hi[0], hi[1]), pack2(hi[2], hi[3]));
    ((uint2*)lp)[i] = make_uint2(pack2(lo[0], lo[1]), pack2(lo[2], lo[3]));
}

// ---------------------------------------------------------------------------
// Depthwise 3x3, pad 1; q/k -> fp32 + fused sum-of-squares, v -> bf16 split
// ---------------------------------------------------------------------------
__global__ __launch_bounds__(256) void dwconv(
    const float* __restrict__ in, const float* __restrict__ w,
    float* __restrict__ outqk, __nv_bfloat16* __restrict__ vh,
    __nv_bfloat16* __restrict__ vl, float* __restrict__ sq)
{
    const int bc = blockIdx.z;             // b*576 + ch
    const int ch = bc % C3;
    const int b = bc / C3;
    const float* ip = in + (size_t)bc * NPIX;
    const float* wp = w + ch * 9;

    const int x = blockIdx.x * 32 + threadIdx.x;
    const int y = blockIdx.y * 8 + threadIdx.y;

    float s = 0.f;
#pragma unroll
    for (int dy = -1; dy <= 1; dy++) {
        int yy = y + dy;
        if ((unsigned)yy < 128u) {
#pragma unroll
            for (int dx = -1; dx <= 1; dx++) {
                int xx = x + dx;
                if ((unsigned)xx < 128u)
                    s = fmaf(__ldg(wp + (dy + 1) * 3 + dx + 1), ip[yy * 128 + xx], s);
            }
        }
    }

    if (ch < DW2) {
        outqk[((size_t)b * DW2 + ch) * NPIX + y * 128 + x] = s;
        __shared__ float red[256];
        int t = threadIdx.y * 32 + threadIdx.x;
        red[t] = s * s;
        __syncthreads();
        for (int off = 128; off; off >>= 1) {
            if (t < off) red[t] += red[t + off];
            __syncthreads();
        }
        if (t == 0) atomicAdd(&sq[b * 2 * CDIM + ch], red[0]);
    } else {
        size_t o = ((size_t)b * CDIM + (ch - DW2)) * NPIX + y * 128 + x;
        __nv_bfloat16 h = __float2bfloat16_rn(s);
        vh[o] = h;
        vl[o] = __float2bfloat16_rn(s - __bfloat162float(h));
    }
}

__global__ void zero_sq(float* __restrict__ sq) {
    int i = blockIdx.x * 256 + threadIdx.x;
    if (i < BDIM * 2 * CDIM) sq[i] = 0.f;
}

__global__ void finalize_norm(const float* __restrict__ sq,
                              float* __restrict__ invn)
{
    int idx = blockIdx.x * 256 + threadIdx.x;
    if (idx >= 2 * BDIM * CDIM) return;
    int which = idx / (BDIM * CDIM);
    int r = idx % (BDIM * CDIM);
    int b = r / CDIM, c = r % CDIM;
    float s = sq[b * 2 * CDIM + which * CDIM + c];
    invn[idx] = 1.0f / fmaxf(sqrtf(s), 1e-12f);
}

// ---------------------------------------------------------------------------
// Partial S[c,d] = sum_n q[c,n]*k[d,n] over a 1/NSPLIT slice of n
// ---------------------------------------------------------------------------
__global__ __launch_bounds__(256) void attn_part(
    const float* __restrict__ dw, float* __restrict__ spart)
{
    const int bh = blockIdx.x;
    const int b = bh >> 2, h = bh & 3;
    const int split = blockIdx.y;
    const float* qb = dw + ((size_t)b * DW2 + h * CPH) * NPIX;
    const float* kb = dw + ((size_t)b * DW2 + CDIM + h * CPH) * NPIX;

    __shared__ float qs[32][CPH + 1];
    __shared__ float ks[32][CPH + 1];

    const int tx = threadIdx.x, ty = threadIdx.y;
    const int tid = ty * 16 + tx;

    float acc[3][3] = {};
    const int nbeg = split * (NPIX / NSPLIT);
    for (int n0 = nbeg; n0 < nbeg + NPIX / NSPLIT; n0 += 32) {
#pragma unroll
        for (int i = 0; i < 6; i++) {
            int idx = tid + i * 256;
            int c = idx >> 5, kk = idx & 31;
            qs[kk][c] = qb[(size_t)c * NPIX + n0 + kk];
            ks[kk][c] = kb[(size_t)c * NPIX + n0 + kk];
        }
        __syncthreads();
#pragma unroll
        for (int kk = 0; kk < 32; kk++) {
            float qa[3], kv[3];
#pragma unroll
            for (int i = 0; i < 3; i++) qa[i] = qs[kk][ty * 3 + i];
#pragma unroll
            for (int j = 0; j < 3; j++) kv[j] = ks[kk][tx * 3 + j];
#pragma unroll
            for (int i = 0; i < 3; i++)
#pragma unroll
                for (int j = 0; j < 3; j++)
                    acc[i][j] = fmaf(qa[i], kv[j], acc[i][j]);
        }
        __syncthreads();
    }

    float* sp = spart + ((size_t)(bh * NSPLIT + split)) * CPH * CPH;
#pragma unroll
    for (int i = 0; i < 3; i++)
#pragma unroll
        for (int j = 0; j < 3; j++)
            sp[(ty * 3 + i) * CPH + tx * 3 + j] = acc[i][j];
}

// ---------------------------------------------------------------------------
// Reduce split-K partials, apply norms + temperature, softmax over d
// ---------------------------------------------------------------------------
__global__ void attn_fin(
    const float* __restrict__ spart, const float* __restrict__ invn,
    const float* __restrict__ temp, float* __restrict__ attn)
{
    const int bh = blockIdx.x;
    const int b = bh >> 2, h = bh & 3;
    const int c = threadIdx.x;
    if (c >= CPH) return;

    const float invq = invn[b * CDIM + h * CPH + c];
    const float t = temp[h];
    const float* base = spart + (size_t)bh * NSPLIT * CPH * CPH + c * CPH;

    float vals[CPH];
    float mx = -1e30f;
#pragma unroll
    for (int d = 0; d < CPH; d++) {
        float s = 0.f;
        for (int sp = 0; sp < NSPLIT; sp++)
            s += base[sp * CPH * CPH + d];
        float invk = invn[BDIM * CDIM + b * CDIM + h * CPH + d];
        float v = s * invq * invk * t;
        vals[d] = v;
        mx = fmaxf(mx, v);
    }
    float sum = 0.f;
#pragma unroll
    for (int d = 0; d < CPH; d++) {
        vals[d] = expf(vals[d] - mx);
        sum += vals[d];
    }
    const float inv = 1.f / sum;
    float* ap = attn + (size_t)bh * CPH * CPH + c * CPH;
#pragma unroll
    for (int d = 0; d < CPH; d++) ap[d] = vals[d] * inv;
}

// ---------------------------------------------------------------------------
// M[b] = proj_w @ blockdiag(attn[b,h]); writes bf16 hi/lo split directly
// ---------------------------------------------------------------------------
__global__ __launch_bounds__(256) void make_M(
    const float* __restrict__ proj, const float* __restrict__ attn,
    __nv_bfloat16* __restrict__ Mh, __nv_bfloat16* __restrict__ Ml)
{
    const int b = blockIdx.x, h = blockIdx.y;
    __shared__ float sA[CPH * CPH];
    const int tid = threadIdx.x;
    const float* ap = attn + ((size_t)(b * NH + h)) * CPH * CPH;
    for (int i = tid; i < CPH * CPH; i += 256) sA[i] = ap[i];
    __syncthreads();

    for (int idx = tid; idx < CDIM * CPH; idx += 256) {
        int oc = idx / CPH, d = idx % CPH;
        float s = 0.f;
#pragma unroll
        for (int c = 0; c < CPH; c++)
            s = fmaf(proj[oc * CDIM + h * CPH + c], sA[c * CPH + d], s);
        size_t o = (size_t)b * CDIM * CDIM + oc * CDIM + h * CPH + d;
        __nv_bfloat16 hh = __float2bfloat16_rn(s);
        Mh[o] = hh;
        Ml[o] = __float2bfloat16_rn(s - __bfloat162float(hh));
    }
}

// ---------------------------------------------------------------------------
extern "C" void kernel_launch(void* const* d_in, const int* in_sizes, int n_in,
                              void* d_out, int out_size)
{
    const float* x      = (const float*)d_in[0];
    const float* qkv_w  = (const float*)d_in[1];
    const float* dw_w   = (const float*)d_in[2];
    const float* proj_w = (const float*)d_in[3];
    const float* temp   = (const float*)d_in[4];
    float* out = (float*)d_out;

    float *qkvp, *dwqkp, *sqp, *invnp, *spartp, *attnp;
    __nv_bfloat16 *vhp, *vlp, *xhp, *xlp, *whp, *wlp, *Mhp, *Mlp;
    cudaGetSymbolAddress((void**)&qkvp,  g_qkv);
    cudaGetSymbolAddress((void**)&dwqkp, g_dwqk);
    cudaGetSymbolAddress((void**)&vhp,   g_vh);
    cudaGetSymbolAddress((void**)&vlp,   g_vl);
    cudaGetSymbolAddress((void**)&xhp,   g_xh);
    cudaGetSymbolAddress((void**)&xlp,   g_xl);
    cudaGetSymbolAddress((void**)&whp,   g_wh);
    cudaGetSymbolAddress((void**)&wlp,   g_wl);
    cudaGetSymbolAddress((void**)&Mhp,   g_Mh);
    cudaGetSymbolAddress((void**)&Mlp,   g_Ml);
    cudaGetSymbolAddress((void**)&sqp,   g_sq);
    cudaGetSymbolAddress((void**)&invnp, g_invnorm);
    cudaGetSymbolAddress((void**)&spartp, g_spart);
    cudaGetSymbolAddress((void**)&attnp, g_attn);

    cudaFuncSetAttribute(gemm_bf16,
        cudaFuncAttributeMaxDynamicSharedMemorySize, SMEM_GEMM);

    // 0) split weights and x into bf16 hi/lo
    {
        int n4 = (C3 * CDIM) / 4;
        split_f32<<<(n4 + 255) / 256, 256>>>(qkv_w, whp, wlp, n4);
    }
    {
        int n4 = (BDIM * CDIM * NPIX) / 4;
        split_f32<<<(n4 + 255) / 256, 256>>>(x, xhp, xlp, n4);
    }

    // 1) qkv = 1x1 conv (pipelined bf16 HMMA)
    gemm_bf16<<<dim3(NPIX / 128, 5, BDIM), 256, SMEM_GEMM>>>(
        whp, wlp, 0L, xhp, xlp, (long)CDIM * NPIX,
        qkvp, (long)C3 * NPIX, C3, NPIX);

    // 2) depthwise 3x3: q/k fp32 + sumsq, v -> bf16 split
    zero_sq<<<(BDIM * 2 * CDIM + 255) / 256, 256>>>(sqp);
    dwconv<<<dim3(128 / 32, 128 / 8, BDIM * C3), dim3(32, 8)>>>(
        qkvp, dw_w, dwqkp, vhp, vlp, sqp);

    // 3) reciprocal row norms
    finalize_norm<<<(2 * BDIM * CDIM + 255) / 256, 256>>>(sqp, invnp);

    // 4) S = q @ k^T  (split-K partials)
    attn_part<<<dim3(BDIM * NH, NSPLIT), dim3(16, 16)>>>(dwqkp, spartp);

    // 5) normalize + temperature + softmax
    attn_fin<<<BDIM * NH, 64>>>(spartp, invnp, temp, attnp);

    // 6) M[b] = proj @ blockdiag(attn) -> bf16 split
    make_M<<<dim3(BDIM, NH), 256>>>(proj_w, attnp, Mhp, Mlp);

    // 7) out[b] = M[b] @ v[b] (pipelined bf16 HMMA)
    gemm_bf16<<<dim3(NPIX / 128, 2, BDIM), 256, SMEM_GEMM>>>(
        Mhp, Mlp, (long)CDIM * CDIM, vhp, vlp, (long)CDIM * NPIX,
        out, (long)CDIM * NPIX, CDIM, NPIX);
}

// round 13
// speedup vs baseline: 2.5318x; 1.1426x over previous
#include <cuda_runtime.h>
#include <cuda_fp16.h>
#include <cstdint>

#define BDIM 8
#define CDIM 192
#define C3 576
#define NPIX 16384
#define NH 4
#define CPH 48
#define NSPLIT 16
#define KTOT 192
#define DW2 (2 * CDIM)   // q+k channels kept in fp32

// ---- scratch (device globals; no allocation allowed) ----
__device__ float g_qkv [(size_t)BDIM * C3 * NPIX];     // after 1x1 conv (fp32)
__device__ float g_dwqk[(size_t)BDIM * DW2 * NPIX];    // dwconv out, q|k only
__device__ __half g_vh[(size_t)BDIM * CDIM * NPIX];    // v fp16 (hi only)
__device__ __half g_xh[(size_t)BDIM * CDIM * NPIX];    // x fp16 (hi only)
__device__ __half g_wh[C3 * CDIM];                     // qkv_w split hi
__device__ __half g_wl[C3 * CDIM];                     // qkv_w split lo
__device__ __half g_Mh[(size_t)BDIM * CDIM * CDIM];
__device__ __half g_Ml[(size_t)BDIM * CDIM * CDIM];
__device__ float g_sq [(size_t)BDIM * 2 * CDIM];
__device__ float g_invnorm[2 * BDIM * CDIM];
__device__ float g_spart[(size_t)BDIM * NH * NSPLIT * CPH * CPH];
__device__ float g_attn [(size_t)BDIM * NH * CPH * CPH];

// ======================= helpers (sm_80+ family-safe) ======================
__device__ __forceinline__ void ldsm_x4(uint32_t* r, uint32_t addr) {
    asm volatile("ldmatrix.sync.aligned.m8n8.x4.shared.b16 {%0,%1,%2,%3}, [%4];"
        : "=r"(r[0]), "=r"(r[1]), "=r"(r[2]), "=r"(r[3]) : "r"(addr));
}
__device__ __forceinline__ void ldsm_x4t(uint32_t* r, uint32_t addr) {
    asm volatile("ldmatrix.sync.aligned.m8n8.x4.trans.shared.b16 {%0,%1,%2,%3}, [%4];"
        : "=r"(r[0]), "=r"(r[1]), "=r"(r[2]), "=r"(r[3]) : "r"(addr));
}
__device__ __forceinline__ void mma16816(float* c, const uint32_t* a,
                                         const uint32_t* b) {
    asm volatile(
        "mma.sync.aligned.m16n8k16.row.col.f32.f16.f16.f32 "
        "{%0,%1,%2,%3}, {%4,%5,%6,%7}, {%8,%9}, {%0,%1,%2,%3};"
        : "+f"(c[0]), "+f"(c[1]), "+f"(c[2]), "+f"(c[3])
        : "r"(a[0]), "r"(a[1]), "r"(a[2]), "r"(a[3]), "r"(b[0]), "r"(b[1]));
}
__device__ __forceinline__ uint32_t packh2(float a, float b) {
    __half2 t = __floats2half2_rn(a, b);
    return *(uint32_t*)&t;
}
__device__ __forceinline__ void cpasync16(uint32_t dst, const void* src, int nb) {
    asm volatile("cp.async.cg.shared.global [%0], [%1], 16, %2;"
                 :: "r"(dst), "l"(src), "r"(nb));
}

// ===========================================================================
// Pipelined fp16 HMMA GEMM, 2-product split: Y = (Ah + Al) @ Bh
//   A pre-split hi/lo fp16 (small: weights / M), B hi-only fp16.
//   Error ~2^-12 (B fp16 rounding) — under 1e-3 threshold.
// CTA 128x128 tile, 8 warps (4m x 2n), K-chunks of 32, 2-stage cp.async.
// ===========================================================================
#define ASTR 40                       // A smem row stride (elems), conflict-free
#define BSTR 136                      // B smem row stride (elems), conflict-free
#define A_ST_B (128 * ASTR * 2)       // 10240 B (one half, one stage)
#define B_ST_B (32 * BSTR * 2)        // 8704 B (one stage)
#define SMEM_GEMM (4 * A_ST_B + 2 * B_ST_B)   // 58368 B

__global__ __launch_bounds__(256, 1)
void gemm_fp16(const __half* __restrict__ Ahg,
               const __half* __restrict__ Alg, long astride,
               const __half* __restrict__ Bhg, long bstride,
               float* __restrict__ Yp, long ystride, int Mrows, int N)
{
    extern __shared__ __align__(16) char sm[];
    const uint32_t sbase = (uint32_t)__cvta_generic_to_shared(sm);

    const int tid = threadIdx.x, lane = tid & 31, wid = tid >> 5;
    const int mw = (wid & 3) * 32, nw = (wid >> 2) * 64;
    const int m0 = blockIdx.y * 128, n0 = blockIdx.x * 128;
    Ahg += (long)blockIdx.z * astride;
    Alg += (long)blockIdx.z * astride;
    Bhg += (long)blockIdx.z * bstride;
    float* Yb = Yp + (long)blockIdx.z * ystride;

    const int arow0 = (mw + (lane & 15)) * ASTR + ((lane >> 4) << 3);
    const int arow1 = arow0 + 16 * ASTR;
    const int brow  = (lane & 15) * BSTR + nw + ((lane >> 4) << 3);

    float acc[2][8][4];
#pragma unroll
    for (int i = 0; i < 2; i++)
#pragma unroll
        for (int j = 0; j < 8; j++)
#pragma unroll
            for (int q = 0; q < 4; q++) acc[i][j][q] = 0.f;

#define LOAD_CHUNK(s, kc) do {                                               \
    uint32_t aB = sbase + (s) * 2 * A_ST_B;                                  \
    uint32_t bB = sbase + 4 * A_ST_B + (s) * B_ST_B;                         \
    _Pragma("unroll")                                                        \
    for (int it = 0; it < 2; it++) {                                         \
        int idx = tid + it * 256;          /* 0..511 */                      \
        int m = idx >> 2, slot = idx & 3;                                    \
        int gm = m0 + m;                                                     \
        uint32_t dst = aB + m * (ASTR * 2) + slot * 16;                      \
        int nb = (gm < Mrows) ? 16 : 0;                                      \
        cpasync16(dst,          Ahg + (long)gm * KTOT + (kc) + slot * 8, nb);\
        cpasync16(dst + A_ST_B, Alg + (long)gm * KTOT + (kc) + slot * 8, nb);\
    }                                                                        \
    _Pragma("unroll")                                                        \
    for (int it = 0; it < 2; it++) {                                         \
        int idx = tid + it * 256;                                            \
        int k = idx >> 4, slot = idx & 15;                                   \
        uint32_t dst = bB + k * (BSTR * 2) + slot * 16;                      \
        cpasync16(dst, Bhg + (long)((kc) + k) * N + n0 + slot * 8, 16);      \
    }                                                                        \
    asm volatile("cp.async.commit_group;");                                  \
} while (0)

    LOAD_CHUNK(0, 0);

    for (int c = 0; c < KTOT / 32; c++) {
        if (c + 1 < KTOT / 32) {
            LOAD_CHUNK((c + 1) & 1, (c + 1) * 32);
            asm volatile("cp.async.wait_group 1;");
        } else {
            asm volatile("cp.async.wait_group 0;");
        }
        __syncthreads();

        const uint32_t aB = sbase + (c & 1) * 2 * A_ST_B;
        const uint32_t sAh = aB, sAl = aB + A_ST_B;
        const uint32_t sBh = sbase + 4 * A_ST_B + (c & 1) * B_ST_B;

#pragma unroll
        for (int ks = 0; ks < 32; ks += 16) {
            uint32_t ah[2][4], al[2][4], bh[8][2];
            ldsm_x4(ah[0], sAh + (uint32_t)(arow0 + ks) * 2);
            ldsm_x4(ah[1], sAh + (uint32_t)(arow1 + ks) * 2);
            ldsm_x4(al[0], sAl + (uint32_t)(arow0 + ks) * 2);
            ldsm_x4(al[1], sAl + (uint32_t)(arow1 + ks) * 2);
#pragma unroll
            for (int p = 0; p < 4; p++) {
                uint32_t r[4];
                ldsm_x4t(r, sBh + (uint32_t)(brow + ks * BSTR + p * 16) * 2);
                bh[2 * p][0] = r[0]; bh[2 * p][1] = r[1];
                bh[2 * p + 1][0] = r[2]; bh[2 * p + 1][1] = r[3];
            }
#pragma unroll
            for (int mf = 0; mf < 2; mf++)
#pragma unroll
                for (int nf = 0; nf < 8; nf++) {
                    mma16816(acc[mf][nf], ah[mf], bh[nf]);  // hi * B
                    mma16816(acc[mf][nf], al[mf], bh[nf]);  // lo * B
                }
        }
        __syncthreads();
    }

    // ---- epilogue: direct STG (fragment layout) ----
#pragma unroll
    for (int mf = 0; mf < 2; mf++) {
        int r0 = m0 + mw + mf * 16 + (lane >> 2);
#pragma unroll
        for (int nf = 0; nf < 8; nf++) {
            int cidx = n0 + nw + nf * 8 + (lane & 3) * 2;
            if (r0 < Mrows)
                *(float2*)&Yb[(long)r0 * N + cidx] =
                    make_float2(acc[mf][nf][0], acc[mf][nf][1]);
            if (r0 + 8 < Mrows)
                *(float2*)&Yb[(long)(r0 + 8) * N + cidx] =
                    make_float2(acc[mf][nf][2], acc[mf][nf][3]);
        }
    }
}

// ---------------------------------------------------------------------------
// fp32 -> (hi, lo) fp16 split, vectorized (n4 = count/4)
// ---------------------------------------------------------------------------
__global__ __launch_bounds__(256) void split_f32(
    const float* __restrict__ in, __half* __restrict__ hp,
    __half* __restrict__ lp, int n4)
{
    int i = blockIdx.x * 256 + threadIdx.x;
    if (i >= n4) return;
    float4 v = ((const float4*)in)[i];
    float vv[4] = {v.x, v.y, v.z, v.w};
    float hi[4], lo[4];
#pragma unroll
    for (int j = 0; j < 4; j++) {
        __half h = __float2half_rn(vv[j]);
        hi[j] = __half2float(h);
        lo[j] = vv[j] - hi[j];
    }
    ((uint2*)hp)[i] = make_uint2(packh2(hi[0], hi[1]), packh2(hi[2], hi[3]));
    ((uint2*)lp)[i] = make_uint2(packh2(lo[0], lo[1]), packh2(lo[2], lo[3]));
}

// fp32 -> fp16 (hi only)
__global__ __launch_bounds__(256) void conv_hi(
    const float* __restrict__ in, __half* __restrict__ hp, int n4)
{
    int i = blockIdx.x * 256 + threadIdx.x;
    if (i >= n4) return;
    float4 v = ((const float4*)in)[i];
    ((uint2*)hp)[i] = make_uint2(packh2(v.x, v.y), packh2(v.z, v.w));
}

// ---------------------------------------------------------------------------
// Depthwise 3x3, pad 1; q/k -> fp32 + fused sum-of-squares, v -> fp16
// ---------------------------------------------------------------------------
__global__ __launch_bounds__(256) void dwconv(
    const float* __restrict__ in, const float* __restrict__ w,
    float* __restrict__ outqk, __half* __restrict__ vh,
    float* __restrict__ sq)
{
    const int bc = blockIdx.z;             // b*576 + ch
    const int ch = bc % C3;
    const int b = bc / C3;
    const float* ip = in + (size_t)bc * NPIX;
    const float* wp = w + ch * 9;

    const int x = blockIdx.x * 32 + threadIdx.x;
    const int y = blockIdx.y * 8 + threadIdx.y;

    float s = 0.f;
#pragma unroll
    for (int dy = -1; dy <= 1; dy++) {
        int yy = y + dy;
        if ((unsigned)yy < 128u) {
#pragma unroll
            for (int dx = -1; dx <= 1; dx++) {
                int xx = x + dx;
                if ((unsigned)xx < 128u)
                    s = fmaf(__ldg(wp + (dy + 1) * 3 + dx + 1), ip[yy * 128 + xx], s);
            }
        }
    }

    if (ch < DW2) {
        outqk[((size_t)b * DW2 + ch) * NPIX + y * 128 + x] = s;
        __shared__ float red[256];
        int t = threadIdx.y * 32 + threadIdx.x;
        red[t] = s * s;
        __syncthreads();
        for (int off = 128; off; off >>= 1) {
            if (t < off) red[t] += red[t + off];
            __syncthreads();
        }
        if (t == 0) atomicAdd(&sq[b * 2 * CDIM + ch], red[0]);
    } else {
        vh[((size_t)b * CDIM + (ch - DW2)) * NPIX + y * 128 + x] =
            __float2half_rn(s);
    }
}

__global__ void zero_sq(float* __restrict__ sq) {
    int i = blockIdx.x * 256 + threadIdx.x;
    if (i < BDIM * 2 * CDIM) sq[i] = 0.f;
}

__global__ void finalize_norm(const float* __restrict__ sq,
                              float* __restrict__ invn)
{
    int idx = blockIdx.x * 256 + threadIdx.x;
    if (idx >= 2 * BDIM * CDIM) return;
    int which = idx / (BDIM * CDIM);
    int r = idx % (BDIM * CDIM);
    int b = r / CDIM, c = r % CDIM;
    float s = sq[b * 2 * CDIM + which * CDIM + c];
    invn[idx] = 1.0f / fmaxf(sqrtf(s), 1e-12f);
}

// ---------------------------------------------------------------------------
// Partial S[c,d] = sum_n q[c,n]*k[d,n] over a 1/NSPLIT slice of n
// ---------------------------------------------------------------------------
__global__ __launch_bounds__(256) void attn_part(
    const float* __restrict__ dw, float* __restrict__ spart)
{
    const int bh = blockIdx.x;
    const int b = bh >> 2, h = bh & 3;
    const int split = blockIdx.y;
    const float* qb = dw + ((size_t)b * DW2 + h * CPH) * NPIX;
    const float* kb = dw + ((size_t)b * DW2 + CDIM + h * CPH) * NPIX;

    __shared__ float qs[32][CPH + 1];
    __shared__ float ks[32][CPH + 1];

    const int tx = threadIdx.x, ty = threadIdx.y;
    const int tid = ty * 16 + tx;

    float acc[3][3] = {};
    const int nbeg = split * (NPIX / NSPLIT);
    for (int n0 = nbeg; n0 < nbeg + NPIX / NSPLIT; n0 += 32) {
#pragma unroll
        for (int i = 0; i < 6; i++) {
            int idx = tid + i * 256;
            int c = idx >> 5, kk = idx & 31;
            qs[kk][c] = qb[(size_t)c * NPIX + n0 + kk];
            ks[kk][c] = kb[(size_t)c * NPIX + n0 + kk];
        }
        __syncthreads();
#pragma unroll
        for (int kk = 0; kk < 32; kk++) {
            float qa[3], kv[3];
#pragma unroll
            for (int i = 0; i < 3; i++) qa[i] = qs[kk][ty * 3 + i];
#pragma unroll
            for (int j = 0; j < 3; j++) kv[j] = ks[kk][tx * 3 + j];
#pragma unroll
            for (int i = 0; i < 3; i++)
#pragma unroll
                for (int j = 0; j < 3; j++)
                    acc[i][j] = fmaf(qa[i], kv[j], acc[i][j]);
        }
        __syncthreads();
    }

    float* sp = spart + ((size_t)(bh * NSPLIT + split)) * CPH * CPH;
#pragma unroll
    for (int i = 0; i < 3; i++)
#pragma unroll
        for (int j = 0; j < 3; j++)
            sp[(ty * 3 + i) * CPH + tx * 3 + j] = acc[i][j];
}

// ---------------------------------------------------------------------------
// Reduce split-K partials, apply norms + temperature, softmax over d
// ---------------------------------------------------------------------------
__global__ void attn_fin(
    const float* __restrict__ spart, const float* __restrict__ invn,
    const float* __restrict__ temp, float* __restrict__ attn)
{
    const int bh = blockIdx.x;
    const int b = bh >> 2, h = bh & 3;
    const int c = threadIdx.x;
    if (c >= CPH) return;

    const float invq = invn[b * CDIM + h * CPH + c];
    const float t = temp[h];
    const float* base = spart + (size_t)bh * NSPLIT * CPH * CPH + c * CPH;

    float vals[CPH];
    float mx = -1e30f;
#pragma unroll
    for (int d = 0; d < CPH; d++) {
        float s = 0.f;
        for (int sp = 0; sp < NSPLIT; sp++)
            s += base[sp * CPH * CPH + d];
        float invk = invn[BDIM * CDIM + b * CDIM + h * CPH + d];
        float v = s * invq * invk * t;
        vals[d] = v;
        mx = fmaxf(mx, v);
    }
    float sum = 0.f;
#pragma unroll
    for (int d = 0; d < CPH; d++) {
        vals[d] = expf(vals[d] - mx);
        sum += vals[d];
    }
    const float inv = 1.f / sum;
    float* ap = attn + (size_t)bh * CPH * CPH + c * CPH;
#pragma unroll
    for (int d = 0; d < CPH; d++) ap[d] = vals[d] * inv;
}

// ---------------------------------------------------------------------------
// M[b] = proj_w @ blockdiag(attn[b,h]); writes fp16 hi/lo split directly
// ---------------------------------------------------------------------------
__global__ __launch_bounds__(256) void make_M(
    const float* __restrict__ proj, const float* __restrict__ attn,
    __half* __restrict__ Mh, __half* __restrict__ Ml)
{
    const int b = blockIdx.x, h = blockIdx.y;
    __shared__ float sA[CPH * CPH];
    const int tid = threadIdx.x;
    const float* ap = attn + ((size_t)(b * NH + h)) * CPH * CPH;
    for (int i = tid; i < CPH * CPH; i += 256) sA[i] = ap[i];
    __syncthreads();

    for (int idx = tid; idx < CDIM * CPH; idx += 256) {
        int oc = idx / CPH, d = idx % CPH;
        float s = 0.f;
#pragma unroll
        for (int c = 0; c < CPH; c++)
            s = fmaf(proj[oc * CDIM + h * CPH + c], sA[c * CPH + d], s);
        size_t o = (size_t)b * CDIM * CDIM + oc * CDIM + h * CPH + d;
        __half hh = __float2half_rn(s);
        Mh[o] = hh;
        Ml[o] = __float2half_rn(s - __half2float(hh));
    }
}

// ---------------------------------------------------------------------------
extern "C" void kernel_launch(void* const* d_in, const int* in_sizes, int n_in,
                              void* d_out, int out_size)
{
    const float* x      = (const float*)d_in[0];
    const float* qkv_w  = (const float*)d_in[1];
    const float* dw_w   = (const float*)d_in[2];
    const float* proj_w = (const float*)d_in[3];
    const float* temp   = (const float*)d_in[4];
    float* out = (float*)d_out;

    float *qkvp, *dwqkp, *sqp, *invnp, *spartp, *attnp;
    __half *vhp, *xhp, *whp, *wlp, *Mhp, *Mlp;
    cudaGetSymbolAddress((void**)&qkvp,  g_qkv);
    cudaGetSymbolAddress((void**)&dwqkp, g_dwqk);
    cudaGetSymbolAddress((void**)&vhp,   g_vh);
    cudaGetSymbolAddress((void**)&xhp,   g_xh);
    cudaGetSymbolAddress((void**)&whp,   g_wh);
    cudaGetSymbolAddress((void**)&wlp,   g_wl);
    cudaGetSymbolAddress((void**)&Mhp,   g_Mh);
    cudaGetSymbolAddress((void**)&Mlp,   g_Ml);
    cudaGetSymbolAddress((void**)&sqp,   g_sq);
    cudaGetSymbolAddress((void**)&invnp, g_invnorm);
    cudaGetSymbolAddress((void**)&spartp, g_spart);
    cudaGetSymbolAddress((void**)&attnp, g_attn);

    cudaFuncSetAttribute(gemm_fp16,
        cudaFuncAttributeMaxDynamicSharedMemorySize, SMEM_GEMM);

    // 0) split weights (hi/lo) and convert x (hi only)
    {
        int n4 = (C3 * CDIM) / 4;
        split_f32<<<(n4 + 255) / 256, 256>>>(qkv_w, whp, wlp, n4);
    }
    {
        int n4 = (BDIM * CDIM * NPIX) / 4;
        conv_hi<<<(n4 + 255) / 256, 256>>>(x, xhp, n4);
    }
    zero_sq<<<(BDIM * 2 * CDIM + 255) / 256, 256>>>(sqp);

    // 1) qkv = 1x1 conv (4th launch -> ncu-profiled next round)
    gemm_fp16<<<dim3(NPIX / 128, 5, BDIM), 256, SMEM_GEMM>>>(
        whp, wlp, 0L, xhp, (long)CDIM * NPIX,
        qkvp, (long)C3 * NPIX, C3, NPIX);

    // 2) depthwise 3x3: q/k fp32 + sumsq, v -> fp16
    dwconv<<<dim3(128 / 32, 128 / 8, BDIM * C3), dim3(32, 8)>>>(
        qkvp, dw_w, dwqkp, vhp, sqp);

    // 3) reciprocal row norms
    finalize_norm<<<(2 * BDIM * CDIM + 255) / 256, 256>>>(sqp, invnp);

    // 4) S = q @ k^T  (split-K partials)
    attn_part<<<dim3(BDIM * NH, NSPLIT), dim3(16, 16)>>>(dwqkp, spartp);

    // 5) normalize + temperature + softmax
    attn_fin<<<BDIM * NH, 64>>>(spartp, invnp, temp, attnp);

    // 6) M[b] = proj @ blockdiag(attn) -> fp16 split
    make_M<<<dim3(BDIM, NH), 256>>>(proj_w, attnp, Mhp, Mlp);

    // 7) out[b] = M[b] @ v[b]
    gemm_fp16<<<dim3(NPIX / 128, 2, BDIM), 256, SMEM_GEMM>>>(
        Mhp, Mlp, (long)CDIM * CDIM, vhp, (long)CDIM * NPIX,
        out, (long)CDIM * NPIX, CDIM, NPIX);
}

// round 15
// speedup vs baseline: 3.0265x; 1.1954x over previous
#include <cuda_runtime.h>
#include <cuda_fp16.h>
#include <cstdint>

#define BDIM 8
#define CDIM 192
#define C3 576
#define NPIX 16384
#define NH 4
#define CPH 48
#define NSPLIT 16
#define KTOT 192

// ---- scratch (device globals; no allocation allowed) ----
__device__ float g_qkv [(size_t)BDIM * C3 * NPIX];     // after 1x1 conv (fp32)
__device__ __half g_qh[(size_t)BDIM * CDIM * NPIX];    // q fp16 hi
__device__ __half g_ql[(size_t)BDIM * CDIM * NPIX];    // q fp16 lo
__device__ __half g_kh[(size_t)BDIM * CDIM * NPIX];    // k fp16 hi
__device__ __half g_vh[(size_t)BDIM * CDIM * NPIX];    // v fp16 hi
__device__ __half g_xh[(size_t)BDIM * CDIM * NPIX];    // x fp16 hi
__device__ __half g_wh[C3 * CDIM];                     // qkv_w split hi
__device__ __half g_wl[C3 * CDIM];                     // qkv_w split lo
__device__ __half g_Mh[(size_t)BDIM * CDIM * CDIM];
__device__ __half g_Ml[(size_t)BDIM * CDIM * CDIM];
__device__ float g_sq [(size_t)BDIM * 2 * CDIM];
__device__ float g_invnorm[2 * BDIM * CDIM];
__device__ float g_S   [(size_t)BDIM * NH * CPH * CPH];  // raw q@k^T
__device__ float g_attn[(size_t)BDIM * NH * CPH * CPH];

// ======================= helpers (sm_80+ family-safe) ======================
__device__ __forceinline__ void ldsm_x4(uint32_t* r, uint32_t addr) {
    asm volatile("ldmatrix.sync.aligned.m8n8.x4.shared.b16 {%0,%1,%2,%3}, [%4];"
        : "=r"(r[0]), "=r"(r[1]), "=r"(r[2]), "=r"(r[3]) : "r"(addr));
}
__device__ __forceinline__ void ldsm_x4t(uint32_t* r, uint32_t addr) {
    asm volatile("ldmatrix.sync.aligned.m8n8.x4.trans.shared.b16 {%0,%1,%2,%3}, [%4];"
        : "=r"(r[0]), "=r"(r[1]), "=r"(r[2]), "=r"(r[3]) : "r"(addr));
}
__device__ __forceinline__ void mma16816(float* c, const uint32_t* a,
                                         const uint32_t* b) {
    asm volatile(
        "mma.sync.aligned.m16n8k16.row.col.f32.f16.f16.f32 "
        "{%0,%1,%2,%3}, {%4,%5,%6,%7}, {%8,%9}, {%0,%1,%2,%3};"
        : "+f"(c[0]), "+f"(c[1]), "+f"(c[2]), "+f"(c[3])
        : "r"(a[0]), "r"(a[1]), "r"(a[2]), "r"(a[3]), "r"(b[0]), "r"(b[1]));
}
__device__ __forceinline__ uint32_t packh2(float a, float b) {
    __half2 t = __floats2half2_rn(a, b);
    return *(uint32_t*)&t;
}
__device__ __forceinline__ void cpasync16(uint32_t dst, const void* src, int nb) {
    asm volatile("cp.async.cg.shared.global [%0], [%1], 16, %2;"
                 :: "r"(dst), "l"(src), "r"(nb));
}

// ===========================================================================
// Pipelined fp16 HMMA GEMM, 2-product split: Y = (Ah + Al) @ Bh
// CTA 128x128 tile, 8 warps (4m x 2n), K-chunks of 32, 2-stage cp.async.
// __launch_bounds__(256,2): cap regs at 128 -> 2 CTAs/SM.
// ===========================================================================
#define ASTR 40
#define BSTR 136
#define A_ST_B (128 * ASTR * 2)       // 10240 B (one half, one stage)
#define B_ST_B (32 * BSTR * 2)        // 8704 B
#define SMEM_GEMM (4 * A_ST_B + 2 * B_ST_B)   // 58368 B

__global__ __launch_bounds__(256, 2)
void gemm_fp16(const __half* __restrict__ Ahg,
               const __half* __restrict__ Alg, long astride,
               const __half* __restrict__ Bhg, long bstride,
               float* __restrict__ Yp, long ystride, int Mrows, int N)
{
    extern __shared__ __align__(16) char sm[];
    const uint32_t sbase = (uint32_t)__cvta_generic_to_shared(sm);

    const int tid = threadIdx.x, lane = tid & 31, wid = tid >> 5;
    const int mw = (wid & 3) * 32, nw = (wid >> 2) * 64;
    const int m0 = blockIdx.y * 128, n0 = blockIdx.x * 128;
    Ahg += (long)blockIdx.z * astride;
    Alg += (long)blockIdx.z * astride;
    Bhg += (long)blockIdx.z * bstride;
    float* Yb = Yp + (long)blockIdx.z * ystride;

    const int arow0 = (mw + (lane & 15)) * ASTR + ((lane >> 4) << 3);
    const int arow1 = arow0 + 16 * ASTR;
    const int brow  = (lane & 15) * BSTR + nw + ((lane >> 4) << 3);

    float acc[2][8][4];
#pragma unroll
    for (int i = 0; i < 2; i++)
#pragma unroll
        for (int j = 0; j < 8; j++)
#pragma unroll
            for (int q = 0; q < 4; q++) acc[i][j][q] = 0.f;

#define LOAD_CHUNK(s, kc) do {                                               \
    uint32_t aB = sbase + (s) * 2 * A_ST_B;                                  \
    uint32_t bB = sbase + 4 * A_ST_B + (s) * B_ST_B;                         \
    _Pragma("unroll")                                                        \
    for (int it = 0; it < 2; it++) {                                         \
        int idx = tid + it * 256;                                            \
        int m = idx >> 2, slot = idx & 3;                                    \
        int gm = m0 + m;                                                     \
        uint32_t dst = aB + m * (ASTR * 2) + slot * 16;                      \
        int nb = (gm < Mrows) ? 16 : 0;                                      \
        cpasync16(dst,          Ahg + (long)gm * KTOT + (kc) + slot * 8, nb);\
        cpasync16(dst + A_ST_B, Alg + (long)gm * KTOT + (kc) + slot * 8, nb);\
    }                                                                        \
    _Pragma("unroll")                                                        \
    for (int it = 0; it < 2; it++) {                                         \
        int idx = tid + it * 256;                                            \
        int k = idx >> 4, slot = idx & 15;                                   \
        uint32_t dst = bB + k * (BSTR * 2) + slot * 16;                      \
        cpasync16(dst, Bhg + (long)((kc) + k) * N + n0 + slot * 8, 16);      \
    }                                                                        \
    asm volatile("cp.async.commit_group;");                                  \
} while (0)

    LOAD_CHUNK(0, 0);

    for (int c = 0; c < KTOT / 32; c++) {
        if (c + 1 < KTOT / 32) {
            LOAD_CHUNK((c + 1) & 1, (c + 1) * 32);
            asm volatile("cp.async.wait_group 1;");
        } else {
            asm volatile("cp.async.wait_group 0;");
        }
        __syncthreads();

        const uint32_t aB = sbase + (c & 1) * 2 * A_ST_B;
        const uint32_t sAh = aB, sAl = aB + A_ST_B;
        const uint32_t sBh = sbase + 4 * A_ST_B + (c & 1) * B_ST_B;

#pragma unroll
        for (int ks = 0; ks < 32; ks += 16) {
            uint32_t ah[2][4], al[2][4], bh[8][2];
            ldsm_x4(ah[0], sAh + (uint32_t)(arow0 + ks) * 2);
            ldsm_x4(ah[1], sAh + (uint32_t)(arow1 + ks) * 2);
            ldsm_x4(al[0], sAl + (uint32_t)(arow0 + ks) * 2);
            ldsm_x4(al[1], sAl + (uint32_t)(arow1 + ks) * 2);
#pragma unroll
            for (int p = 0; p < 4; p++) {
                uint32_t r[4];
                ldsm_x4t(r, sBh + (uint32_t)(brow + ks * BSTR + p * 16) * 2);
                bh[2 * p][0] = r[0]; bh[2 * p][1] = r[1];
                bh[2 * p + 1][0] = r[2]; bh[2 * p + 1][1] = r[3];
            }
#pragma unroll
            for (int mf = 0; mf < 2; mf++)
#pragma unroll
                for (int nf = 0; nf < 8; nf++) {
                    mma16816(acc[mf][nf], ah[mf], bh[nf]);
                    mma16816(acc[mf][nf], al[mf], bh[nf]);
                }
        }
        __syncthreads();
    }

#pragma unroll
    for (int mf = 0; mf < 2; mf++) {
        int r0 = m0 + mw + mf * 16 + (lane >> 2);
#pragma unroll
        for (int nf = 0; nf < 8; nf++) {
            int cidx = n0 + nw + nf * 8 + (lane & 3) * 2;
            if (r0 < Mrows)
                *(float2*)&Yb[(long)r0 * N + cidx] =
                    make_float2(acc[mf][nf][0], acc[mf][nf][1]);
            if (r0 + 8 < Mrows)
                *(float2*)&Yb[(long)(r0 + 8) * N + cidx] =
                    make_float2(acc[mf][nf][2], acc[mf][nf][3]);
        }
    }
}

// ---------------------------------------------------------------------------
// fp32 -> (hi, lo) fp16 split / hi-only convert
// ---------------------------------------------------------------------------
__global__ __launch_bounds__(256) void split_f32(
    const float* __restrict__ in, __half* __restrict__ hp,
    __half* __restrict__ lp, int n4)
{
    int i = blockIdx.x * 256 + threadIdx.x;
    if (i >= n4) return;
    float4 v = ((const float4*)in)[i];
    float vv[4] = {v.x, v.y, v.z, v.w};
    float hi[4], lo[4];
#pragma unroll
    for (int j = 0; j < 4; j++) {
        __half h = __float2half_rn(vv[j]);
        hi[j] = __half2float(h);
        lo[j] = vv[j] - hi[j];
    }
    ((uint2*)hp)[i] = make_uint2(packh2(hi[0], hi[1]), packh2(hi[2], hi[3]));
    ((uint2*)lp)[i] = make_uint2(packh2(lo[0], lo[1]), packh2(lo[2], lo[3]));
}

__global__ __launch_bounds__(256) void conv_hi(
    const float* __restrict__ in, __half* __restrict__ hp, int n4)
{
    int i = blockIdx.x * 256 + threadIdx.x;
    if (i >= n4) return;
    float4 v = ((const float4*)in)[i];
    ((uint2*)hp)[i] = make_uint2(packh2(v.x, v.y), packh2(v.z, v.w));
}

// ---------------------------------------------------------------------------
// Depthwise 3x3, pad 1; q -> fp16 hi/lo, k -> fp16 hi, v -> fp16 hi;
// q/k sum-of-squares fused (computed in fp32).
// ---------------------------------------------------------------------------
__global__ __launch_bounds__(256) void dwconv(
    const float* __restrict__ in, const float* __restrict__ w,
    __half* __restrict__ qh, __half* __restrict__ ql,
    __half* __restrict__ kh, __half* __restrict__ vh,
    float* __restrict__ sq)
{
    const int bc = blockIdx.z;             // b*576 + ch
    const int ch = bc % C3;
    const int b = bc / C3;
    const float* ip = in + (size_t)bc * NPIX;
    const float* wp = w + ch * 9;

    const int x = blockIdx.x * 32 + threadIdx.x;
    const int y = blockIdx.y * 8 + threadIdx.y;

    float s = 0.f;
#pragma unroll
    for (int dy = -1; dy <= 1; dy++) {
        int yy = y + dy;
        if ((unsigned)yy < 128u) {
#pragma unroll
            for (int dx = -1; dx <= 1; dx++) {
                int xx = x + dx;
                if ((unsigned)xx < 128u)
                    s = fmaf(__ldg(wp + (dy + 1) * 3 + dx + 1), ip[yy * 128 + xx], s);
            }
        }
    }

    const int pix = y * 128 + x;
    if (ch < CDIM) {                                    // q
        size_t o = ((size_t)b * CDIM + ch) * NPIX + pix;
        __half h = __float2half_rn(s);
        qh[o] = h;
        ql[o] = __float2half_rn(s - __half2float(h));
    } else if (ch < 2 * CDIM) {                         // k
        kh[((size_t)b * CDIM + (ch - CDIM)) * NPIX + pix] = __float2half_rn(s);
    } else {                                            // v
        vh[((size_t)b * CDIM + (ch - 2 * CDIM)) * NPIX + pix] = __float2half_rn(s);
    }

    if (ch < 2 * CDIM) {
        __shared__ float red[256];
        int t = threadIdx.y * 32 + threadIdx.x;
        red[t] = s * s;
        __syncthreads();
        for (int off = 128; off; off >>= 1) {
            if (t < off) red[t] += red[t + off];
            __syncthreads();
        }
        if (t == 0) atomicAdd(&sq[b * 2 * CDIM + ch], red[0]);
    }
}

// zero sumsq + raw-S accumulators
__global__ void zero_all(float* __restrict__ sq, float* __restrict__ S) {
    int i = blockIdx.x * 256 + threadIdx.x;
    if (i < BDIM * 2 * CDIM) sq[i] = 0.f;
    if (i < BDIM * NH * CPH * CPH) S[i] = 0.f;
}

__global__ void finalize_norm(const float* __restrict__ sq,
                              float* __restrict__ invn)
{
    int idx = blockIdx.x * 256 + threadIdx.x;
    if (idx >= 2 * BDIM * CDIM) return;
    int which = idx / (BDIM * CDIM);
    int r = idx % (BDIM * CDIM);
    int b = r / CDIM, c = r % CDIM;
    float s = sq[b * 2 * CDIM + which * CDIM + c];
    invn[idx] = 1.0f / fmaxf(sqrtf(s), 1e-12f);
}

// ---------------------------------------------------------------------------
// S[bh] += (qh+ql) @ kh^T over a 1/NSPLIT n-slice, via HMMA.
// Block: 256 thr / 8 warps. Per iter: stage 48x128 of qh,ql,kh in smem;
// warp w does the 16-n k-chunk w. AtomicAdd fp32 partials into g_S.
// ---------------------------------------------------------------------------
#define QSTR 136     // smem row stride in halves (272 B, conflict-free)
#define NS_IT (NPIX / NSPLIT / 128)   // 8 iterations of 128 n

__global__ __launch_bounds__(256) void attn_part_hmma(
    const __half* __restrict__ qh, const __half* __restrict__ ql,
    const __half* __restrict__ kh, float* __restrict__ S)
{
    const int bh = blockIdx.x;           // 0..31
    const int b = bh >> 2, h = bh & 3;
    const int split = blockIdx.y;
    const size_t chbase = ((size_t)b * CDIM + h * CPH) * NPIX;
    const __half* qhb = qh + chbase;
    const __half* qlb = ql + chbase;
    const __half* khb = kh + chbase;

    __shared__ __align__(16) __half sQ[CPH * QSTR];
    __shared__ __align__(16) __half sL[CPH * QSTR];
    __shared__ __align__(16) __half sK[CPH * QSTR];
    const uint32_t aQ = (uint32_t)__cvta_generic_to_shared(sQ);
    const uint32_t aL = (uint32_t)__cvta_generic_to_shared(sL);
    const uint32_t aK = (uint32_t)__cvta_generic_to_shared(sK);

    const int tid = threadIdx.x, lane = tid & 31, wid = tid >> 5;
    const int k0 = wid * 16;             // this warp's n-chunk within 128

    // A-fragment address component (rows = q channels)
    const int aoff = ((lane & 15) * QSTR + k0 + ((lane >> 4) << 3)) * 2;
    // B-fragment address: rows = k channels (n-dim), non-trans ldmatrix
    const int g1 = (lane >> 3) & 1;      // k-half
    const int g2 = lane >> 4;            // n-tile within pair
    const int boff_r = (g2 * 8 + (lane & 7));  // row add within pair base
    const int boff = (boff_r * QSTR + k0 + g1 * 8) * 2;

    float acc[3][6][4];
#pragma unroll
    for (int i = 0; i < 3; i++)
#pragma unroll
        for (int j = 0; j < 6; j++)
#pragma unroll
            for (int q = 0; q < 4; q++) acc[i][j][q] = 0.f;

    const int nbeg = split * (NPIX / NSPLIT);
    for (int it = 0; it < NS_IT; it++) {
        const int n0 = nbeg + it * 128;
        // stage 48 rows x 128 halves of each array (768 x 16B per array)
        for (int i = tid; i < CPH * 16; i += 256) {
            int r = i >> 4, s8 = i & 15;
            uint32_t d = (uint32_t)(r * QSTR * 2 + s8 * 16);
            const size_t g = (size_t)r * NPIX + n0 + s8 * 8;
            cpasync16(aQ + d, qhb + g, 16);
            cpasync16(aL + d, qlb + g, 16);
            cpasync16(aK + d, khb + g, 16);
        }
        asm volatile("cp.async.commit_group;");
        asm volatile("cp.async.wait_group 0;");
        __syncthreads();

        uint32_t afh[3][4], afl[3][4], bf[6][2];
#pragma unroll
        for (int mf = 0; mf < 3; mf++) {
            ldsm_x4(afh[mf], aQ + mf * 16 * QSTR * 2 + aoff);
            ldsm_x4(afl[mf], aL + mf * 16 * QSTR * 2 + aoff);
        }
#pragma unroll
        for (int p = 0; p < 3; p++) {
            uint32_t r[4];
            ldsm_x4(r, aK + (p * 16) * QSTR * 2 + boff);
            bf[2 * p][0] = r[0]; bf[2 * p][1] = r[1];
            bf[2 * p + 1][0] = r[2]; bf[2 * p + 1][1] = r[3];
        }
#pragma unroll
        for (int mf = 0; mf < 3; mf++)
#pragma unroll
            for (int nf = 0; nf < 6; nf++) {
                mma16816(acc[mf][nf], afh[mf], bf[nf]);
                mma16816(acc[mf][nf], afl[mf], bf[nf]);
            }
        __syncthreads();
    }

    float* Sb = S + (size_t)bh * CPH * CPH;
#pragma unroll
    for (int mf = 0; mf < 3; mf++) {
        int r0 = mf * 16 + (lane >> 2);
#pragma unroll
        for (int nf = 0; nf < 6; nf++) {
            int c = nf * 8 + (lane & 3) * 2;
            atomicAdd(&Sb[r0 * CPH + c],        acc[mf][nf][0]);
            atomicAdd(&Sb[r0 * CPH + c + 1],    acc[mf][nf][1]);
            atomicAdd(&Sb[(r0 + 8) * CPH + c],     acc[mf][nf][2]);
            atomicAdd(&Sb[(r0 + 8) * CPH + c + 1], acc[mf][nf][3]);
        }
    }
}

// ---------------------------------------------------------------------------
// Apply norms + temperature, softmax over d
// ---------------------------------------------------------------------------
__global__ void attn_fin(
    const float* __restrict__ S, const float* __restrict__ invn,
    const float* __restrict__ temp, float* __restrict__ attn)
{
    const int bh = blockIdx.x;
    const int b = bh >> 2, h = bh & 3;
    const int c = threadIdx.x;
    if (c >= CPH) return;

    const float invq = invn[b * CDIM + h * CPH + c];
    const float t = temp[h];
    const float* base = S + (size_t)bh * CPH * CPH + c * CPH;

    float vals[CPH];
    float mx = -1e30f;
#pragma unroll
    for (int d = 0; d < CPH; d++) {
        float invk = invn[BDIM * CDIM + b * CDIM + h * CPH + d];
        float v = base[d] * invq * invk * t;
        vals[d] = v;
        mx = fmaxf(mx, v);
    }
    float sum = 0.f;
#pragma unroll
    for (int d = 0; d < CPH; d++) {
        vals[d] = expf(vals[d] - mx);
        sum += vals[d];
    }
    const float inv = 1.f / sum;
    float* ap = attn + (size_t)bh * CPH * CPH + c * CPH;
#pragma unroll
    for (int d = 0; d < CPH; d++) ap[d] = vals[d] * inv;
}

// ---------------------------------------------------------------------------
// M[b] = proj_w @ blockdiag(attn[b,h]); writes fp16 hi/lo split directly
// ---------------------------------------------------------------------------
__global__ __launch_bounds__(256) void make_M(
    const float* __restrict__ proj, const float* __restrict__ attn,
    __half* __restrict__ Mh, __half* __restrict__ Ml)
{
    const int b = blockIdx.x, h = blockIdx.y;
    __shared__ float sA[CPH * CPH];
    const int tid = threadIdx.x;
    const float* ap = attn + ((size_t)(b * NH + h)) * CPH * CPH;
    for (int i = tid; i < CPH * CPH; i += 256) sA[i] = ap[i];
    __syncthreads();

    for (int idx = tid; idx < CDIM * CPH; idx += 256) {
        int oc = idx / CPH, d = idx % CPH;
        float s = 0.f;
#pragma unroll
        for (int c = 0; c < CPH; c++)
            s = fmaf(proj[oc * CDIM + h * CPH + c], sA[c * CPH + d], s);
        size_t o = (size_t)b * CDIM * CDIM + oc * CDIM + h * CPH + d;
        __half hh = __float2half_rn(s);
        Mh[o] = hh;
        Ml[o] = __float2half_rn(s - __half2float(hh));
    }
}

// ---------------------------------------------------------------------------
extern "C" void kernel_launch(void* const* d_in, const int* in_sizes, int n_in,
                              void* d_out, int out_size)
{
    const float* x      = (const float*)d_in[0];
    const float* qkv_w  = (const float*)d_in[1];
    const float* dw_w   = (const float*)d_in[2];
    const float* proj_w = (const float*)d_in[3];
    const float* temp   = (const float*)d_in[4];
    float* out = (float*)d_out;

    float *qkvp, *sqp, *invnp, *Sp, *attnp;
    __half *qhp, *qlp, *khp, *vhp, *xhp, *whp, *wlp, *Mhp, *Mlp;
    cudaGetSymbolAddress((void**)&qkvp,  g_qkv);
    cudaGetSymbolAddress((void**)&qhp,   g_qh);
    cudaGetSymbolAddress((void**)&qlp,   g_ql);
    cudaGetSymbolAddress((void**)&khp,   g_kh);
    cudaGetSymbolAddress((void**)&vhp,   g_vh);
    cudaGetSymbolAddress((void**)&xhp,   g_xh);
    cudaGetSymbolAddress((void**)&whp,   g_wh);
    cudaGetSymbolAddress((void**)&wlp,   g_wl);
    cudaGetSymbolAddress((void**)&Mhp,   g_Mh);
    cudaGetSymbolAddress((void**)&Mlp,   g_Ml);
    cudaGetSymbolAddress((void**)&sqp,   g_sq);
    cudaGetSymbolAddress((void**)&invnp, g_invnorm);
    cudaGetSymbolAddress((void**)&Sp,    g_S);
    cudaGetSymbolAddress((void**)&attnp, g_attn);

    cudaFuncSetAttribute(gemm_fp16,
        cudaFuncAttributeMaxDynamicSharedMemorySize, SMEM_GEMM);

    // 0) split weights (hi/lo), convert x (hi only), zero accumulators
    {
        int n4 = (C3 * CDIM) / 4;
        split_f32<<<(n4 + 255) / 256, 256>>>(qkv_w, whp, wlp, n4);
    }
    {
        int n4 = (BDIM * CDIM * NPIX) / 4;
        conv_hi<<<(n4 + 255) / 256, 256>>>(x, xhp, n4);
    }
    zero_all<<<(BDIM * NH * CPH * CPH + 255) / 256, 256>>>(sqp, Sp);

    // 1) qkv = 1x1 conv (4th launch -> ncu-profiled)
    gemm_fp16<<<dim3(NPIX / 128, 5, BDIM), 256, SMEM_GEMM>>>(
        whp, wlp, 0L, xhp, (long)CDIM * NPIX,
        qkvp, (long)C3 * NPIX, C3, NPIX);

    // 2) depthwise 3x3: q->fp16 hi/lo, k/v->fp16, fused sumsq
    dwconv<<<dim3(128 / 32, 128 / 8, BDIM * C3), dim3(32, 8)>>>(
        qkvp, dw_w, qhp, qlp, khp, vhp, sqp);

    // 3) reciprocal row norms
    finalize_norm<<<(2 * BDIM * CDIM + 255) / 256, 256>>>(sqp, invnp);

    // 4) S = q @ k^T (HMMA, split-K atomics)
    attn_part_hmma<<<dim3(BDIM * NH, NSPLIT), 256>>>(qhp, qlp, khp, Sp);

    // 5) normalize + temperature + softmax
    attn_fin<<<BDIM * NH, 64>>>(Sp, invnp, temp, attnp);

    // 6) M[b] = proj @ blockdiag(attn) -> fp16 split
    make_M<<<dim3(BDIM, NH), 256>>>(proj_w, attnp, Mhp, Mlp);

    // 7) out[b] = M[b] @ v[b]
    gemm_fp16<<<dim3(NPIX / 128, 2, BDIM), 256, SMEM_GEMM>>>(
        Mhp, Mlp, (long)CDIM * CDIM, vhp, (long)CDIM * NPIX,
        out, (long)CDIM * NPIX, CDIM, NPIX);
}

// round 16
// speedup vs baseline: 3.0330x; 1.0021x over previous
#include <cuda_runtime.h>
#include <cuda_fp16.h>
#include <cstdint>

#define BDIM 8
#define CDIM 192
#define C3 576
#define NPIX 16384
#define NH 4
#define CPH 48
#define NSPLIT 16
#define KTOT 192

// ---- scratch (device globals; no allocation allowed) ----
__device__ __half g_qkvh[(size_t)BDIM * C3 * NPIX];    // after 1x1 conv (fp16)
__device__ __half g_qh[(size_t)BDIM * CDIM * NPIX];    // q fp16 hi
__device__ __half g_ql[(size_t)BDIM * CDIM * NPIX];    // q fp16 lo
__device__ __half g_kh[(size_t)BDIM * CDIM * NPIX];    // k fp16 hi
__device__ __half g_vh[(size_t)BDIM * CDIM * NPIX];    // v fp16 hi
__device__ __half g_xh[(size_t)BDIM * CDIM * NPIX];    // x fp16 hi
__device__ __half g_wh[C3 * CDIM];                     // qkv_w split hi
__device__ __half g_wl[C3 * CDIM];                     // qkv_w split lo
__device__ __half g_Mh[(size_t)BDIM * CDIM * CDIM];
__device__ __half g_Ml[(size_t)BDIM * CDIM * CDIM];
__device__ float g_sq [(size_t)BDIM * 2 * CDIM];
__device__ float g_invnorm[2 * BDIM * CDIM];
__device__ float g_S   [(size_t)BDIM * NH * CPH * CPH];  // raw q@k^T
__device__ float g_attn[(size_t)BDIM * NH * CPH * CPH];

// ======================= helpers (sm_80+ family-safe) ======================
__device__ __forceinline__ void ldsm_x4(uint32_t* r, uint32_t addr) {
    asm volatile("ldmatrix.sync.aligned.m8n8.x4.shared.b16 {%0,%1,%2,%3}, [%4];"
        : "=r"(r[0]), "=r"(r[1]), "=r"(r[2]), "=r"(r[3]) : "r"(addr));
}
__device__ __forceinline__ void ldsm_x4t(uint32_t* r, uint32_t addr) {
    asm volatile("ldmatrix.sync.aligned.m8n8.x4.trans.shared.b16 {%0,%1,%2,%3}, [%4];"
        : "=r"(r[0]), "=r"(r[1]), "=r"(r[2]), "=r"(r[3]) : "r"(addr));
}
__device__ __forceinline__ void mma16816(float* c, const uint32_t* a,
                                         const uint32_t* b) {
    asm volatile(
        "mma.sync.aligned.m16n8k16.row.col.f32.f16.f16.f32 "
        "{%0,%1,%2,%3}, {%4,%5,%6,%7}, {%8,%9}, {%0,%1,%2,%3};"
        : "+f"(c[0]), "+f"(c[1]), "+f"(c[2]), "+f"(c[3])
        : "r"(a[0]), "r"(a[1]), "r"(a[2]), "r"(a[3]), "r"(b[0]), "r"(b[1]));
}
__device__ __forceinline__ uint32_t packh2(float a, float b) {
    __half2 t = __floats2half2_rn(a, b);
    return *(uint32_t*)&t;
}
__device__ __forceinline__ void cpasync16(uint32_t dst, const void* src, int nb) {
    asm volatile("cp.async.cg.shared.global [%0], [%1], 16, %2;"
                 :: "r"(dst), "l"(src), "r"(nb));
}

// ===========================================================================
// Pipelined fp16 HMMA GEMM, 2-product split: Y = (Ah + Al) @ Bh
// CTA 128x128 tile, 8 warps (4m x 2n), K-chunks of 32, 3-stage cp.async.
// HALF_OUT: write __half output (gemm1 -> qkv) vs float (gemm2 -> out).
// ===========================================================================
#define ASTR 40
#define BSTR 136
#define A_ST_B (128 * ASTR * 2)       // 10240 B (one half, one stage)
#define B_ST_B (32 * BSTR * 2)        // 8704 B
#define NSTG 3
#define NC (KTOT / 32)                // 6 chunks
#define SMEM_GEMM (NSTG * 2 * A_ST_B + NSTG * B_ST_B)   // 87552 B

template<int HALF_OUT>
__global__ __launch_bounds__(256, 2)
void gemm_fp16(const __half* __restrict__ Ahg,
               const __half* __restrict__ Alg, long astride,
               const __half* __restrict__ Bhg, long bstride,
               void* __restrict__ Yp, long ystride, int Mrows, int N)
{
    extern __shared__ __align__(16) char sm[];
    const uint32_t sbase = (uint32_t)__cvta_generic_to_shared(sm);

    const int tid = threadIdx.x, lane = tid & 31, wid = tid >> 5;
    const int mw = (wid & 3) * 32, nw = (wid >> 2) * 64;
    const int m0 = blockIdx.y * 128, n0 = blockIdx.x * 128;
    Ahg += (long)blockIdx.z * astride;
    Alg += (long)blockIdx.z * astride;
    Bhg += (long)blockIdx.z * bstride;

    const int arow0 = (mw + (lane & 15)) * ASTR + ((lane >> 4) << 3);
    const int arow1 = arow0 + 16 * ASTR;
    const int brow  = (lane & 15) * BSTR + nw + ((lane >> 4) << 3);

    float acc[2][8][4];
#pragma unroll
    for (int i = 0; i < 2; i++)
#pragma unroll
        for (int j = 0; j < 8; j++)
#pragma unroll
            for (int q = 0; q < 4; q++) acc[i][j][q] = 0.f;

#define LOAD_CHUNK(s, kc) do {                                               \
    uint32_t aB = sbase + (s) * 2 * A_ST_B;                                  \
    uint32_t bB = sbase + NSTG * 2 * A_ST_B + (s) * B_ST_B;                  \
    _Pragma("unroll")                                                        \
    for (int it = 0; it < 2; it++) {                                         \
        int idx = tid + it * 256;                                            \
        int m = idx >> 2, slot = idx & 3;                                    \
        int gm = m0 + m;                                                     \
        uint32_t dst = aB + m * (ASTR * 2) + slot * 16;                      \
        int nb = (gm < Mrows) ? 16 : 0;                                      \
        cpasync16(dst,          Ahg + (long)gm * KTOT + (kc) + slot * 8, nb);\
        cpasync16(dst + A_ST_B, Alg + (long)gm * KTOT + (kc) + slot * 8, nb);\
    }                                                                        \
    _Pragma("unroll")                                                        \
    for (int it = 0; it < 2; it++) {                                         \
        int idx = tid + it * 256;                                            \
        int k = idx >> 4, slot = idx & 15;                                   \
        uint32_t dst = bB + k * (BSTR * 2) + slot * 16;                      \
        cpasync16(dst, Bhg + (long)((kc) + k) * N + n0 + slot * 8, 16);      \
    }                                                                        \
    asm volatile("cp.async.commit_group;");                                  \
} while (0)

    LOAD_CHUNK(0, 0);
    LOAD_CHUNK(1, 32);

    for (int c = 0; c < NC; c++) {
        if (c + 1 < NC) asm volatile("cp.async.wait_group 1;");
        else            asm volatile("cp.async.wait_group 0;");
        __syncthreads();
        if (c + 2 < NC) LOAD_CHUNK((c + 2) % NSTG, (c + 2) * 32);

        const int st = c % NSTG;
        const uint32_t aB = sbase + st * 2 * A_ST_B;
        const uint32_t sAh = aB, sAl = aB + A_ST_B;
        const uint32_t sBh = sbase + NSTG * 2 * A_ST_B + st * B_ST_B;

#pragma unroll
        for (int ks = 0; ks < 32; ks += 16) {
            uint32_t ah[2][4], al[2][4], bh[8][2];
            ldsm_x4(ah[0], sAh + (uint32_t)(arow0 + ks) * 2);
            ldsm_x4(ah[1], sAh + (uint32_t)(arow1 + ks) * 2);
            ldsm_x4(al[0], sAl + (uint32_t)(arow0 + ks) * 2);
            ldsm_x4(al[1], sAl + (uint32_t)(arow1 + ks) * 2);
#pragma unroll
            for (int p = 0; p < 4; p++) {
                uint32_t r[4];
                ldsm_x4t(r, sBh + (uint32_t)(brow + ks * BSTR + p * 16) * 2);
                bh[2 * p][0] = r[0]; bh[2 * p][1] = r[1];
                bh[2 * p + 1][0] = r[2]; bh[2 * p + 1][1] = r[3];
            }
#pragma unroll
            for (int mf = 0; mf < 2; mf++)
#pragma unroll
                for (int nf = 0; nf < 8; nf++) {
                    mma16816(acc[mf][nf], ah[mf], bh[nf]);
                    mma16816(acc[mf][nf], al[mf], bh[nf]);
                }
        }
        __syncthreads();
    }

    // ---- epilogue ----
    if (HALF_OUT) {
        __half* Yb = (__half*)Yp + (long)blockIdx.z * ystride;
#pragma unroll
        for (int mf = 0; mf < 2; mf++) {
            int r0 = m0 + mw + mf * 16 + (lane >> 2);
#pragma unroll
            for (int nf = 0; nf < 8; nf++) {
                int cidx = n0 + nw + nf * 8 + (lane & 3) * 2;
                if (r0 < Mrows)
                    *(uint32_t*)&Yb[(long)r0 * N + cidx] =
                        packh2(acc[mf][nf][0], acc[mf][nf][1]);
                if (r0 + 8 < Mrows)
                    *(uint32_t*)&Yb[(long)(r0 + 8) * N + cidx] =
                        packh2(acc[mf][nf][2], acc[mf][nf][3]);
            }
        }
    } else {
        float* Yb = (float*)Yp + (long)blockIdx.z * ystride;
#pragma unroll
        for (int mf = 0; mf < 2; mf++) {
            int r0 = m0 + mw + mf * 16 + (lane >> 2);
#pragma unroll
            for (int nf = 0; nf < 8; nf++) {
                int cidx = n0 + nw + nf * 8 + (lane & 3) * 2;
                if (r0 < Mrows)
                    *(float2*)&Yb[(long)r0 * N + cidx] =
                        make_float2(acc[mf][nf][0], acc[mf][nf][1]);
                if (r0 + 8 < Mrows)
                    *(float2*)&Yb[(long)(r0 + 8) * N + cidx] =
                        make_float2(acc[mf][nf][2], acc[mf][nf][3]);
            }
        }
    }
}

// ---------------------------------------------------------------------------
// fp32 -> (hi, lo) fp16 split / hi-only convert
// ---------------------------------------------------------------------------
__global__ __launch_bounds__(256) void split_f32(
    const float* __restrict__ in, __half* __restrict__ hp,
    __half* __restrict__ lp, int n4)
{
    int i = blockIdx.x * 256 + threadIdx.x;
    if (i >= n4) return;
    float4 v = ((const float4*)in)[i];
    float vv[4] = {v.x, v.y, v.z, v.w};
    float hi[4], lo[4];
#pragma unroll
    for (int j = 0; j < 4; j++) {
        __half h = __float2half_rn(vv[j]);
        hi[j] = __half2float(h);
        lo[j] = vv[j] - hi[j];
    }
    ((uint2*)hp)[i] = make_uint2(packh2(hi[0], hi[1]), packh2(hi[2], hi[3]));
    ((uint2*)lp)[i] = make_uint2(packh2(lo[0], lo[1]), packh2(lo[2], lo[3]));
}

__global__ __launch_bounds__(256) void conv_hi(
    const float* __restrict__ in, __half* __restrict__ hp, int n4)
{
    int i = blockIdx.x * 256 + threadIdx.x;
    if (i >= n4) return;
    float4 v = ((const float4*)in)[i];
    ((uint2*)hp)[i] = make_uint2(packh2(v.x, v.y), packh2(v.z, v.w));
}

// ---------------------------------------------------------------------------
// Depthwise 3x3 (fp16 input), pad 1; q -> fp16 hi/lo, k/v -> fp16 hi;
// q/k sum-of-squares fused (computed in fp32).
// ---------------------------------------------------------------------------
__global__ __launch_bounds__(256) void dwconv(
    const __half* __restrict__ in, const float* __restrict__ w,
    __half* __restrict__ qh, __half* __restrict__ ql,
    __half* __restrict__ kh, __half* __restrict__ vh,
    float* __restrict__ sq)
{
    const int bc = blockIdx.z;             // b*576 + ch
    const int ch = bc % C3;
    const int b = bc / C3;
    const __half* ip = in + (size_t)bc * NPIX;
    const float* wp = w + ch * 9;

    const int x = blockIdx.x * 32 + threadIdx.x;
    const int y = blockIdx.y * 8 + threadIdx.y;

    float s = 0.f;
#pragma unroll
    for (int dy = -1; dy <= 1; dy++) {
        int yy = y + dy;
        if ((unsigned)yy < 128u) {
#pragma unroll
            for (int dx = -1; dx <= 1; dx++) {
                int xx = x + dx;
                if ((unsigned)xx < 128u)
                    s = fmaf(__ldg(wp + (dy + 1) * 3 + dx + 1),
                             __half2float(ip[yy * 128 + xx]), s);
            }
        }
    }

    const int pix = y * 128 + x;
    if (ch < CDIM) {                                    // q
        size_t o = ((size_t)b * CDIM + ch) * NPIX + pix;
        __half h = __float2half_rn(s);
        qh[o] = h;
        ql[o] = __float2half_rn(s - __half2float(h));
    } else if (ch < 2 * CDIM) {                         // k
        kh[((size_t)b * CDIM + (ch - CDIM)) * NPIX + pix] = __float2half_rn(s);
    } else {                                            // v
        vh[((size_t)b * CDIM + (ch - 2 * CDIM)) * NPIX + pix] = __float2half_rn(s);
    }

    if (ch < 2 * CDIM) {
        __shared__ float red[256];
        int t = threadIdx.y * 32 + threadIdx.x;
        red[t] = s * s;
        __syncthreads();
        for (int off = 128; off; off >>= 1) {
            if (t < off) red[t] += red[t + off];
            __syncthreads();
        }
        if (t == 0) atomicAdd(&sq[b * 2 * CDIM + ch], red[0]);
    }
}

// zero sumsq + raw-S accumulators
__global__ void zero_all(float* __restrict__ sq, float* __restrict__ S) {
    int i = blockIdx.x * 256 + threadIdx.x;
    if (i < BDIM * 2 * CDIM) sq[i] = 0.f;
    if (i < BDIM * NH * CPH * CPH) S[i] = 0.f;
}

__global__ void finalize_norm(const float* __restrict__ sq,
                              float* __restrict__ invn)
{
    int idx = blockIdx.x * 256 + threadIdx.x;
    if (idx >= 2 * BDIM * CDIM) return;
    int which = idx / (BDIM * CDIM);
    int r = idx % (BDIM * CDIM);
    int b = r / CDIM, c = r % CDIM;
    float s = sq[b * 2 * CDIM + which * CDIM + c];
    invn[idx] = 1.0f / fmaxf(sqrtf(s), 1e-12f);
}

// ---------------------------------------------------------------------------
// S[bh] += (qh+ql) @ kh^T over a 1/NSPLIT n-slice, via HMMA.
// ---------------------------------------------------------------------------
#define QSTR 136
#define NS_IT (NPIX / NSPLIT / 128)   // 8 iterations of 128 n

__global__ __launch_bounds__(256) void attn_part_hmma(
    const __half* __restrict__ qh, const __half* __restrict__ ql,
    const __half* __restrict__ kh, float* __restrict__ S)
{
    const int bh = blockIdx.x;
    const int b = bh >> 2, h = bh & 3;
    const int split = blockIdx.y;
    const size_t chbase = ((size_t)b * CDIM + h * CPH) * NPIX;
    const __half* qhb = qh + chbase;
    const __half* qlb = ql + chbase;
    const __half* khb = kh + chbase;

    __shared__ __align__(16) __half sQ[CPH * QSTR];
    __shared__ __align__(16) __half sL[CPH * QSTR];
    __shared__ __align__(16) __half sK[CPH * QSTR];
    const uint32_t aQ = (uint32_t)__cvta_generic_to_shared(sQ);
    const uint32_t aL = (uint32_t)__cvta_generic_to_shared(sL);
    const uint32_t aK = (uint32_t)__cvta_generic_to_shared(sK);

    const int tid = threadIdx.x, lane = tid & 31, wid = tid >> 5;
    const int k0 = wid * 16;

    const int aoff = ((lane & 15) * QSTR + k0 + ((lane >> 4) << 3)) * 2;
    const int g1 = (lane >> 3) & 1;
    const int g2 = lane >> 4;
    const int boff_r = (g2 * 8 + (lane & 7));
    const int boff = (boff_r * QSTR + k0 + g1 * 8) * 2;

    float acc[3][6][4];
#pragma unroll
    for (int i = 0; i < 3; i++)
#pragma unroll
        for (int j = 0; j < 6; j++)
#pragma unroll
            for (int q = 0; q < 4; q++) acc[i][j][q] = 0.f;

    const int nbeg = split * (NPIX / NSPLIT);
    for (int it = 0; it < NS_IT; it++) {
        const int n0 = nbeg + it * 128;
        for (int i = tid; i < CPH * 16; i += 256) {
            int r = i >> 4, s8 = i & 15;
            uint32_t d = (uint32_t)(r * QSTR * 2 + s8 * 16);
            const size_t g = (size_t)r * NPIX + n0 + s8 * 8;
            cpasync16(aQ + d, qhb + g, 16);
            cpasync16(aL + d, qlb + g, 16);
            cpasync16(aK + d, khb + g, 16);
        }
        asm volatile("cp.async.commit_group;");
        asm volatile("cp.async.wait_group 0;");
        __syncthreads();

        uint32_t afh[3][4], afl[3][4], bf[6][2];
#pragma unroll
        for (int mf = 0; mf < 3; mf++) {
            ldsm_x4(afh[mf], aQ + mf * 16 * QSTR * 2 + aoff);
            ldsm_x4(afl[mf], aL + mf * 16 * QSTR * 2 + aoff);
        }
#pragma unroll
        for (int p = 0; p < 3; p++) {
            uint32_t r[4];
            ldsm_x4(r, aK + (p * 16) * QSTR * 2 + boff);
            bf[2 * p][0] = r[0]; bf[2 * p][1] = r[1];
            bf[2 * p + 1][0] = r[2]; bf[2 * p + 1][1] = r[3];
        }
#pragma unroll
        for (int mf = 0; mf < 3; mf++)
#pragma unroll
            for (int nf = 0; nf < 6; nf++) {
                mma16816(acc[mf][nf], afh[mf], bf[nf]);
                mma16816(acc[mf][nf], afl[mf], bf[nf]);
            }
        __syncthreads();
    }

    float* Sb = S + (size_t)bh * CPH * CPH;
#pragma unroll
    for (int mf = 0; mf < 3; mf++) {
        int r0 = mf * 16 + (lane >> 2);
#pragma unroll
        for (int nf = 0; nf < 6; nf++) {
            int c = nf * 8 + (lane & 3) * 2;
            atomicAdd(&Sb[r0 * CPH + c],        acc[mf][nf][0]);
            atomicAdd(&Sb[r0 * CPH + c + 1],    acc[mf][nf][1]);
            atomicAdd(&Sb[(r0 + 8) * CPH + c],     acc[mf][nf][2]);
            atomicAdd(&Sb[(r0 + 8) * CPH + c + 1], acc[mf][nf][3]);
        }
    }
}

// ---------------------------------------------------------------------------
// Apply norms + temperature, softmax over d
// ---------------------------------------------------------------------------
__global__ void attn_fin(
    const float* __restrict__ S, const float* __restrict__ invn,
    const float* __restrict__ temp, float* __restrict__ attn)
{
    const int bh = blockIdx.x;
    const int b = bh >> 2, h = bh & 3;
    const int c = threadIdx.x;
    if (c >= CPH) return;

    const float invq = invn[b * CDIM + h * CPH + c];
    const float t = temp[h];
    const float* base = S + (size_t)bh * CPH * CPH + c * CPH;

    float vals[CPH];
    float mx = -1e30f;
#pragma unroll
    for (int d = 0; d < CPH; d++) {
        float invk = invn[BDIM * CDIM + b * CDIM + h * CPH + d];
        float v = base[d] * invq * invk * t;
        vals[d] = v;
        mx = fmaxf(mx, v);
    }
    float sum = 0.f;
#pragma unroll
    for (int d = 0; d < CPH; d++) {
        vals[d] = expf(vals[d] - mx);
        sum += vals[d];
    }
    const float inv = 1.f / sum;
    float* ap = attn + (size_t)bh * CPH * CPH + c * CPH;
#pragma unroll
    for (int d = 0; d < CPH; d++) ap[d] = vals[d] * inv;
}

// ---------------------------------------------------------------------------
// M[b] = proj_w @ blockdiag(attn[b,h]); writes fp16 hi/lo split directly
// ---------------------------------------------------------------------------
__global__ __launch_bounds__(256) void make_M(
    const float* __restrict__ proj, const float* __restrict__ attn,
    __half* __restrict__ Mh, __half* __restrict__ Ml)
{
    const int b = blockIdx.x, h = blockIdx.y;
    __shared__ float sA[CPH * CPH];
    const int tid = threadIdx.x;
    const float* ap = attn + ((size_t)(b * NH + h)) * CPH * CPH;
    for (int i = tid; i < CPH * CPH; i += 256) sA[i] = ap[i];
    __syncthreads();

    for (int idx = tid; idx < CDIM * CPH; idx += 256) {
        int oc = idx / CPH, d = idx % CPH;
        float s = 0.f;
#pragma unroll
        for (int c = 0; c < CPH; c++)
            s = fmaf(proj[oc * CDIM + h * CPH + c], sA[c * CPH + d], s);
        size_t o = (size_t)b * CDIM * CDIM + oc * CDIM + h * CPH + d;
        __half hh = __float2half_rn(s);
        Mh[o] = hh;
        Ml[o] = __float2half_rn(s - __half2float(hh));
    }
}

// ---------------------------------------------------------------------------
extern "C" void kernel_launch(void* const* d_in, const int* in_sizes, int n_in,
                              void* d_out, int out_size)
{
    const float* x      = (const float*)d_in[0];
    const float* qkv_w  = (const float*)d_in[1];
    const float* dw_w   = (const float*)d_in[2];
    const float* proj_w = (const float*)d_in[3];
    const float* temp   = (const float*)d_in[4];
    float* out = (float*)d_out;

    float *sqp, *invnp, *Sp, *attnp;
    __half *qkvhp, *qhp, *qlp, *khp, *vhp, *xhp, *whp, *wlp, *Mhp, *Mlp;
    cudaGetSymbolAddress((void**)&qkvhp, g_qkvh);
    cudaGetSymbolAddress((void**)&qhp,   g_qh);
    cudaGetSymbolAddress((void**)&qlp,   g_ql);
    cudaGetSymbolAddress((void**)&khp,   g_kh);
    cudaGetSymbolAddress((void**)&vhp,   g_vh);
    cudaGetSymbolAddress((void**)&xhp,   g_xh);
    cudaGetSymbolAddress((void**)&whp,   g_wh);
    cudaGetSymbolAddress((void**)&wlp,   g_wl);
    cudaGetSymbolAddress((void**)&Mhp,   g_Mh);
    cudaGetSymbolAddress((void**)&Mlp,   g_Ml);
    cudaGetSymbolAddress((void**)&sqp,   g_sq);
    cudaGetSymbolAddress((void**)&invnp, g_invnorm);
    cudaGetSymbolAddress((void**)&Sp,    g_S);
    cudaGetSymbolAddress((void**)&attnp, g_attn);

    cudaFuncSetAttribute(gemm_fp16<1>,
        cudaFuncAttributeMaxDynamicSharedMemorySize, SMEM_GEMM);
    cudaFuncSetAttribute(gemm_fp16<0>,
        cudaFuncAttributeMaxDynamicSharedMemorySize, SMEM_GEMM);

    // 0) split weights (hi/lo), convert x (hi only), zero accumulators
    {
        int n4 = (C3 * CDIM) / 4;
        split_f32<<<(n4 + 255) / 256, 256>>>(qkv_w, whp, wlp, n4);
    }
    {
        int n4 = (BDIM * CDIM * NPIX) / 4;
        conv_hi<<<(n4 + 255) / 256, 256>>>(x, xhp, n4);
    }
    zero_all<<<(BDIM * NH * CPH * CPH + 255) / 256, 256>>>(sqp, Sp);

    // 1) qkv = 1x1 conv, fp16 output (4th launch -> ncu-profiled)
    gemm_fp16<1><<<dim3(NPIX / 128, 5, BDIM), 256, SMEM_GEMM>>>(
        whp, wlp, 0L, xhp, (long)CDIM * NPIX,
        qkvhp, (long)C3 * NPIX, C3, NPIX);

    // 2) depthwise 3x3 (fp16 in): q->fp16 hi/lo, k/v->fp16, fused sumsq
    dwconv<<<dim3(128 / 32, 128 / 8, BDIM * C3), dim3(32, 8)>>>(
        qkvhp, dw_w, qhp, qlp, khp, vhp, sqp);

    // 3) reciprocal row norms
    finalize_norm<<<(2 * BDIM * CDIM + 255) / 256, 256>>>(sqp, invnp);

    // 4) S = q @ k^T (HMMA, split-K atomics)
    attn_part_hmma<<<dim3(BDIM * NH, NSPLIT), 256>>>(qhp, qlp, khp, Sp);

    // 5) normalize + temperature + softmax
    attn_fin<<<BDIM * NH, 64>>>(Sp, invnp, temp, attnp);

    // 6) M[b] = proj @ blockdiag(attn) -> fp16 split
    make_M<<<dim3(BDIM, NH), 256>>>(proj_w, attnp, Mhp, Mlp);

    // 7) out[b] = M[b] @ v[b], fp32 output
    gemm_fp16<0><<<dim3(NPIX / 128, 2, BDIM), 256, SMEM_GEMM>>>(
        Mhp, Mlp, (long)CDIM * CDIM, vhp, (long)CDIM * NPIX,
        out, (long)CDIM * NPIX, CDIM, NPIX);
}